// round 5
// baseline (speedup 1.0000x reference)
#include <cuda_runtime.h>
#include <cuda_bf16.h>
#include <math_constants.h>
#include <cstdint>

// Problem constants
#define B_  2
#define S_  2048
#define H_  1024
#define NH_ 16
#define HD_ 64
#define MROWS_ (B_ * S_)          // 4096
#define LN_ROWS_ (B_ * S_ * NH_)  // 65536

// Scratch (device globals — allocation-free rule)
__device__ float g_qkv[(size_t)MROWS_ * 3 * H_];  // [4096, 3072]
__device__ float g_qh [(size_t)MROWS_ * H_];      // [B*NH, S, HD]
__device__ float g_kh [(size_t)MROWS_ * H_];
__device__ float g_ctx[(size_t)MROWS_ * H_];      // [B, S, H]

// ---------------------------------------------------------------------------
// tf32 / ldmatrix helpers
// ---------------------------------------------------------------------------
__device__ __forceinline__ float tf32r(float x) {
    float y;
    asm("cvt.rna.tf32.f32 %0, %1;" : "=f"(y) : "f"(x));
    return y;
}

__device__ __forceinline__ void mma_tf32(float c[4], const uint32_t a[4],
                                         const uint32_t b[2]) {
    asm volatile(
        "mma.sync.aligned.m16n8k8.row.col.f32.tf32.tf32.f32 "
        "{%0,%1,%2,%3}, {%4,%5,%6,%7}, {%8,%9}, {%0,%1,%2,%3};"
        : "+f"(c[0]), "+f"(c[1]), "+f"(c[2]), "+f"(c[3])
        : "r"(a[0]), "r"(a[1]), "r"(a[2]), "r"(a[3]), "r"(b[0]), "r"(b[1]));
}

__device__ __forceinline__ void ldsm_x4(uint32_t r[4], uint32_t addr) {
    asm volatile("ldmatrix.sync.aligned.m8n8.x4.shared.b16 {%0,%1,%2,%3}, [%4];"
                 : "=r"(r[0]), "=r"(r[1]), "=r"(r[2]), "=r"(r[3]) : "r"(addr));
}

__device__ __forceinline__ void ldsm_x2(uint32_t r[2], uint32_t addr) {
    asm volatile("ldmatrix.sync.aligned.m8n8.x2.shared.b16 {%0,%1}, [%2];"
                 : "=r"(r[0]), "=r"(r[1]) : "r"(addr));
}

// ---------------------------------------------------------------------------
// TF32 tensor-core GEMM: C[M,N] = A[M,K] @ B[K,N] + bias[N]
// 128x128 tile, BK=16 double-buffered. 8 warps of 64x32 (4x4 m16n8k8).
// Fragment loads via ldmatrix:
//   As2[m][k]  row stride 20 -> 16B row chunks at 80B stride: conflict-free
//   Bsn[n][k]  row stride 20 -> same; B stored K-contiguous for LDSM
// ---------------------------------------------------------------------------
#define AP 20

__global__ __launch_bounds__(256, 2) void gemm_tf32(
    const float* __restrict__ A, const float* __restrict__ Bm,
    const float* __restrict__ bias, float* __restrict__ C,
    int M, int N, int K)
{
    __shared__ float As2[2][128][AP];
    __shared__ float Bsn[2][128][AP];

    const int tid  = threadIdx.x;
    const int lane = tid & 31;
    const int warp = tid >> 5;
    const int wm = (warp & 1) * 64;
    const int wn = (warp >> 1) * 32;
    const int gid = lane >> 2;
    const int tig = lane & 3;
    const int brow = blockIdx.y * 128;
    const int bcol = blockIdx.x * 128;

    // A global->smem mapping (unchanged from R3; conflict-checked)
    const int aRow = tid >> 2;        // 0..63 (+64)
    const int aCol = (tid & 3) * 4;   // 0,4,8,12
    const float* Aptr  = A + (size_t)(brow + aRow) * K + aCol;
    const float* Aptr2 = Aptr + (size_t)64 * K;

    // B global->smem: thread covers n = lane + 32*(warp&3), k = 8*(warp>>2)+0..7
    const int bN = lane + 32 * (warp & 3);
    const int bK = 8 * (warp >> 2);
    const float* Bptr = Bm + (size_t)bK * N + bcol + bN;

    // ldmatrix per-thread source coords
    const int lrowA = (((lane >> 3) & 1) * 8) + (lane & 7);  // row within 16
    const int lcolA = (lane >> 4) * 4;                        // 0 or 4
    const int lrowB = lane & 7;                               // n within 8
    const int lcolB = ((lane >> 3) & 1) * 4;                  // 0 or 4

    float c[4][4][4];
#pragma unroll
    for (int i = 0; i < 4; i++)
#pragma unroll
        for (int j = 0; j < 4; j++)
#pragma unroll
            for (int r = 0; r < 4; r++) c[i][j][r] = 0.f;

    float4 av0, av1;
    float bv[8];

    // prologue: tile 0
    av0 = *(const float4*)(Aptr);
    av1 = *(const float4*)(Aptr2);
#pragma unroll
    for (int j = 0; j < 8; j++) bv[j] = Bptr[(size_t)j * N];
    {
        float4 a0 = make_float4(tf32r(av0.x), tf32r(av0.y), tf32r(av0.z), tf32r(av0.w));
        float4 a1 = make_float4(tf32r(av1.x), tf32r(av1.y), tf32r(av1.z), tf32r(av1.w));
        *(float4*)&As2[0][aRow][aCol]      = a0;
        *(float4*)&As2[0][aRow + 64][aCol] = a1;
        float4 b0 = make_float4(tf32r(bv[0]), tf32r(bv[1]), tf32r(bv[2]), tf32r(bv[3]));
        float4 b1 = make_float4(tf32r(bv[4]), tf32r(bv[5]), tf32r(bv[6]), tf32r(bv[7]));
        *(float4*)&Bsn[0][bN][bK]     = b0;
        *(float4*)&Bsn[0][bN][bK + 4] = b1;
    }
    __syncthreads();

    const uint32_t smemA = (uint32_t)__cvta_generic_to_shared(&As2[0][0][0]);
    const uint32_t smemB = (uint32_t)__cvta_generic_to_shared(&Bsn[0][0][0]);
    const uint32_t bufStride = 128 * AP * 4;   // bytes per buffer
    // per-thread ldsm base offsets (buffer 0, mt/nt/ks = 0)
    const uint32_t aOff = ((uint32_t)(wm + lrowA) * AP + lcolA) * 4;
    const uint32_t bOff = ((uint32_t)(wn + lrowB) * AP + lcolB) * 4;

    const int iters = K / 16;
    for (int t = 0; t < iters; t++) {
        const int buf = t & 1;
        if (t + 1 < iters) {
            const int k0 = (t + 1) * 16;
            av0 = *(const float4*)(Aptr + k0);
            av1 = *(const float4*)(Aptr2 + k0);
#pragma unroll
            for (int j = 0; j < 8; j++) bv[j] = Bptr[(size_t)(k0 + j) * N];
        }

        const uint32_t aBase = smemA + buf * bufStride + aOff;
        const uint32_t bBase = smemB + buf * bufStride + bOff;
#pragma unroll
        for (int ks = 0; ks < 2; ks++) {
            uint32_t af[4][4], bf[4][2];
#pragma unroll
            for (int mt = 0; mt < 4; mt++)
                ldsm_x4(af[mt], aBase + (uint32_t)(mt * 16 * AP + ks * 8) * 4);
#pragma unroll
            for (int nt = 0; nt < 4; nt++)
                ldsm_x2(bf[nt], bBase + (uint32_t)(nt * 8 * AP + ks * 8) * 4);
#pragma unroll
            for (int mt = 0; mt < 4; mt++)
#pragma unroll
                for (int nt = 0; nt < 4; nt++)
                    mma_tf32(c[mt][nt], af[mt], bf[nt]);
        }

        if (t + 1 < iters) {
            const int nb = (t + 1) & 1;
            float4 a0 = make_float4(tf32r(av0.x), tf32r(av0.y), tf32r(av0.z), tf32r(av0.w));
            float4 a1 = make_float4(tf32r(av1.x), tf32r(av1.y), tf32r(av1.z), tf32r(av1.w));
            *(float4*)&As2[nb][aRow][aCol]      = a0;
            *(float4*)&As2[nb][aRow + 64][aCol] = a1;
            float4 b0 = make_float4(tf32r(bv[0]), tf32r(bv[1]), tf32r(bv[2]), tf32r(bv[3]));
            float4 b1 = make_float4(tf32r(bv[4]), tf32r(bv[5]), tf32r(bv[6]), tf32r(bv[7]));
            *(float4*)&Bsn[nb][bN][bK]     = b0;
            *(float4*)&Bsn[nb][bN][bK + 4] = b1;
            __syncthreads();
        }
    }

    // epilogue: bias add + store
#pragma unroll
    for (int mt = 0; mt < 4; mt++) {
        const int row = brow + wm + mt * 16 + gid;
#pragma unroll
        for (int nt = 0; nt < 4; nt++) {
            const int col = bcol + wn + nt * 8 + tig * 2;
            const float b0 = bias[col], b1 = bias[col + 1];
            float2 o0 = make_float2(c[mt][nt][0] + b0, c[mt][nt][1] + b1);
            float2 o1 = make_float2(c[mt][nt][2] + b0, c[mt][nt][3] + b1);
            *(float2*)&C[(size_t)row * N + col]       = o0;
            *(float2*)&C[(size_t)(row + 8) * N + col] = o1;
        }
    }
}

// ---------------------------------------------------------------------------
// Split QKV + per-head LayerNorm on Q,K (HD=64). V stays in qkv (read direct).
// ---------------------------------------------------------------------------
__global__ __launch_bounds__(256) void qkv_split_ln(
    const float* __restrict__ qkv,
    const float* __restrict__ qg, const float* __restrict__ qb,
    const float* __restrict__ kg, const float* __restrict__ kb,
    float* __restrict__ qh, float* __restrict__ kh)
{
    int w = (blockIdx.x * blockDim.x + threadIdx.x) >> 5;
    int lane = threadIdx.x & 31;
    int t = w / LN_ROWS_;      // 0:q 1:k
    int row = w - t * LN_ROWS_;
    if (t >= 2) return;

    int b = row / (S_ * NH_);
    int rem = row - b * (S_ * NH_);
    int s = rem / NH_;
    int n = rem - s * NH_;

    const float* src = qkv + (size_t)(b * S_ + s) * (3 * H_) + t * H_ + n * HD_;
    float* dst = (t == 0 ? qh : kh) + ((size_t)(b * NH_ + n) * S_ + s) * HD_;

    float x0 = src[lane];
    float x1 = src[lane + 32];

    float s1 = x0 + x1;
    float s2 = x0 * x0 + x1 * x1;
#pragma unroll
    for (int o = 16; o > 0; o >>= 1) {
        s1 += __shfl_xor_sync(0xffffffffu, s1, o);
        s2 += __shfl_xor_sync(0xffffffffu, s2, o);
    }
    float mu  = s1 * (1.0f / HD_);
    float var = s2 * (1.0f / HD_) - mu * mu;
    float inv = rsqrtf(var + 1e-5f);

    const float* g  = (t == 0) ? qg : kg;
    const float* be = (t == 0) ? qb : kb;
    dst[lane]      = (x0 - mu) * inv * g[lane]      + be[lane];
    dst[lane + 32] = (x1 - mu) * inv * g[lane + 32] + be[lane + 32];
}

// ---------------------------------------------------------------------------
// Causal flash attention, TF32 tensor cores. V read directly from qkv.
// ---------------------------------------------------------------------------
__global__ __launch_bounds__(128, 3) void flash_attn_tc(
    const float* __restrict__ qh, const float* __restrict__ kh,
    const float* __restrict__ qkv, float* __restrict__ ctx)
{
    __shared__ float Ks[32][68];
    __shared__ float Vs[32][72];
    __shared__ float Ps[64][36];

    const int bh  = blockIdx.y;
    const int qt  = blockIdx.x;
    const int tid = threadIdx.x;
    const int lane = tid & 31;
    const int w    = tid >> 5;
    const int gid  = lane >> 2;
    const int tig  = lane & 3;
    const int qbase = qt * 64;
    const int wrow  = w * 16;

    const int bb = bh >> 4;
    const int nh = bh & 15;

    const float* Q  = qh + (size_t)bh * S_ * HD_ + (size_t)qbase * HD_;
    const float* Kp = kh + (size_t)bh * S_ * HD_;
    const float* Vq = qkv + (size_t)bb * S_ * 3 * H_ + 2 * H_ + nh * HD_;

    uint32_t qa[8][4];
#pragma unroll
    for (int h = 0; h < 2; h++) {
        for (int i = tid; i < 64 * 8; i += 128) {
            int r = i >> 3, c4 = (i & 7) * 4;
            float4 v = *(const float4*)&Q[r * HD_ + h * 32 + c4];
            Ps[r][c4 + 0] = tf32r(v.x);
            Ps[r][c4 + 1] = tf32r(v.y);
            Ps[r][c4 + 2] = tf32r(v.z);
            Ps[r][c4 + 3] = tf32r(v.w);
        }
        __syncthreads();
#pragma unroll
        for (int ks = 0; ks < 4; ks++) {
            qa[h * 4 + ks][0] = __float_as_uint(Ps[wrow + gid][ks * 8 + tig]);
            qa[h * 4 + ks][1] = __float_as_uint(Ps[wrow + gid + 8][ks * 8 + tig]);
            qa[h * 4 + ks][2] = __float_as_uint(Ps[wrow + gid][ks * 8 + tig + 4]);
            qa[h * 4 + ks][3] = __float_as_uint(Ps[wrow + gid + 8][ks * 8 + tig + 4]);
        }
        __syncthreads();
    }

    float o[8][4];
#pragma unroll
    for (int i = 0; i < 8; i++)
#pragma unroll
        for (int j = 0; j < 4; j++) o[i][j] = 0.f;
    float m0 = -CUDART_INF_F, m1 = -CUDART_INF_F;
    float l0 = 0.f, l1 = 0.f;

    const int r0g = qbase + wrow + gid;
    const int r1g = r0g + 8;
    const int rmaxw = qbase + wrow + 15;
    const int nkt = (qt + 1) * 2;
    const float scl = 0.125f;

    for (int kt = 0; kt < nkt; kt++) {
        const int kbase = kt * 32;
        for (int i = tid; i < 32 * 16; i += 128) {
            int r = i >> 4, c4 = (i & 15) * 4;
            const float* kp = &Kp[(size_t)(kbase + r) * HD_ + c4];
            float4 kv = *(const float4*)kp;
            Ks[r][c4 + 0] = tf32r(kv.x); Ks[r][c4 + 1] = tf32r(kv.y);
            Ks[r][c4 + 2] = tf32r(kv.z); Ks[r][c4 + 3] = tf32r(kv.w);
            const float* vp = &Vq[(size_t)(kbase + r) * 3 * H_ + c4];
            float4 vv = *(const float4*)vp;
            Vs[r][c4 + 0] = tf32r(vv.x); Vs[r][c4 + 1] = tf32r(vv.y);
            Vs[r][c4 + 2] = tf32r(vv.z); Vs[r][c4 + 3] = tf32r(vv.w);
        }
        __syncthreads();

        if (kbase <= rmaxw) {
            float s[4][4];
#pragma unroll
            for (int nt = 0; nt < 4; nt++)
#pragma unroll
                for (int j = 0; j < 4; j++) s[nt][j] = 0.f;
#pragma unroll
            for (int nt = 0; nt < 4; nt++) {
#pragma unroll
                for (int ks = 0; ks < 8; ks++) {
                    uint32_t b[2];
                    b[0] = __float_as_uint(Ks[nt * 8 + gid][ks * 8 + tig]);
                    b[1] = __float_as_uint(Ks[nt * 8 + gid][ks * 8 + tig + 4]);
                    mma_tf32(s[nt], qa[ks], b);
                }
            }

            if (kbase + 31 <= qbase + wrow) {
#pragma unroll
                for (int nt = 0; nt < 4; nt++)
#pragma unroll
                    for (int j = 0; j < 4; j++) s[nt][j] *= scl;
            } else {
#pragma unroll
                for (int nt = 0; nt < 4; nt++) {
                    int c0 = kbase + nt * 8 + tig * 2;
                    s[nt][0] = (c0     <= r0g) ? s[nt][0] * scl : -CUDART_INF_F;
                    s[nt][1] = (c0 + 1 <= r0g) ? s[nt][1] * scl : -CUDART_INF_F;
                    s[nt][2] = (c0     <= r1g) ? s[nt][2] * scl : -CUDART_INF_F;
                    s[nt][3] = (c0 + 1 <= r1g) ? s[nt][3] * scl : -CUDART_INF_F;
                }
            }

            float mt0 = fmaxf(fmaxf(s[0][0], s[0][1]), fmaxf(s[1][0], s[1][1]));
            mt0 = fmaxf(mt0, fmaxf(fmaxf(s[2][0], s[2][1]), fmaxf(s[3][0], s[3][1])));
            float mt1 = fmaxf(fmaxf(s[0][2], s[0][3]), fmaxf(s[1][2], s[1][3]));
            mt1 = fmaxf(mt1, fmaxf(fmaxf(s[2][2], s[2][3]), fmaxf(s[3][2], s[3][3])));
            mt0 = fmaxf(mt0, __shfl_xor_sync(0xffffffffu, mt0, 1));
            mt0 = fmaxf(mt0, __shfl_xor_sync(0xffffffffu, mt0, 2));
            mt1 = fmaxf(mt1, __shfl_xor_sync(0xffffffffu, mt1, 1));
            mt1 = fmaxf(mt1, __shfl_xor_sync(0xffffffffu, mt1, 2));

            float mn0 = fmaxf(m0, mt0), mn1 = fmaxf(m1, mt1);
            float a0 = __expf(m0 - mn0), a1 = __expf(m1 - mn1);
            m0 = mn0; m1 = mn1;

            float ps0 = 0.f, ps1 = 0.f;
#pragma unroll
            for (int nt = 0; nt < 4; nt++) {
                float p0 = tf32r(__expf(s[nt][0] - mn0));
                float p1 = tf32r(__expf(s[nt][1] - mn0));
                float p2 = tf32r(__expf(s[nt][2] - mn1));
                float p3 = tf32r(__expf(s[nt][3] - mn1));
                ps0 += p0 + p1;
                ps1 += p2 + p3;
                Ps[wrow + gid][nt * 8 + tig * 2 + 0]     = p0;
                Ps[wrow + gid][nt * 8 + tig * 2 + 1]     = p1;
                Ps[wrow + gid + 8][nt * 8 + tig * 2 + 0] = p2;
                Ps[wrow + gid + 8][nt * 8 + tig * 2 + 1] = p3;
            }
            ps0 += __shfl_xor_sync(0xffffffffu, ps0, 1);
            ps0 += __shfl_xor_sync(0xffffffffu, ps0, 2);
            ps1 += __shfl_xor_sync(0xffffffffu, ps1, 1);
            ps1 += __shfl_xor_sync(0xffffffffu, ps1, 2);
            l0 = l0 * a0 + ps0;
            l1 = l1 * a1 + ps1;

#pragma unroll
            for (int nt = 0; nt < 8; nt++) {
                o[nt][0] *= a0; o[nt][1] *= a0;
                o[nt][2] *= a1; o[nt][3] *= a1;
            }

            uint32_t pa[4][4];
#pragma unroll
            for (int ks = 0; ks < 4; ks++) {
                pa[ks][0] = __float_as_uint(Ps[wrow + gid][ks * 8 + tig]);
                pa[ks][1] = __float_as_uint(Ps[wrow + gid + 8][ks * 8 + tig]);
                pa[ks][2] = __float_as_uint(Ps[wrow + gid][ks * 8 + tig + 4]);
                pa[ks][3] = __float_as_uint(Ps[wrow + gid + 8][ks * 8 + tig + 4]);
            }
#pragma unroll
            for (int nt = 0; nt < 8; nt++) {
#pragma unroll
                for (int ks = 0; ks < 4; ks++) {
                    uint32_t b[2];
                    b[0] = __float_as_uint(Vs[ks * 8 + tig][nt * 8 + gid]);
                    b[1] = __float_as_uint(Vs[ks * 8 + tig + 4][nt * 8 + gid]);
                    mma_tf32(o[nt], pa[ks], b);
                }
            }
        }
        __syncthreads();
    }

    const float inv0 = 1.0f / l0;
    const float inv1 = 1.0f / l1;
    float* orow0 = ctx + (size_t)(bb * S_ + r0g) * H_ + nh * HD_;
    float* orow1 = ctx + (size_t)(bb * S_ + r1g) * H_ + nh * HD_;
#pragma unroll
    for (int nt = 0; nt < 8; nt++) {
        int col = nt * 8 + tig * 2;
        *(float2*)&orow0[col] = make_float2(o[nt][0] * inv0, o[nt][1] * inv0);
        *(float2*)&orow1[col] = make_float2(o[nt][2] * inv1, o[nt][3] * inv1);
    }
}

// ---------------------------------------------------------------------------
extern "C" void kernel_launch(void* const* d_in, const int* in_sizes, int n_in,
                              void* d_out, int out_size)
{
    const float* hs = (const float*)d_in[0];
    const float* Wa = (const float*)d_in[1];
    const float* ba = (const float*)d_in[2];
    const float* Wp = (const float*)d_in[3];
    const float* bp = (const float*)d_in[4];
    const float* qg = (const float*)d_in[5];
    const float* qb = (const float*)d_in[6];
    const float* kg = (const float*)d_in[7];
    const float* kb = (const float*)d_in[8];
    float* out = (float*)d_out;

    float *qkv, *qh, *kh, *ctx;
    cudaGetSymbolAddress((void**)&qkv, g_qkv);
    cudaGetSymbolAddress((void**)&qh,  g_qh);
    cudaGetSymbolAddress((void**)&kh,  g_kh);
    cudaGetSymbolAddress((void**)&ctx, g_ctx);

    // 1) QKV GEMM: [4096,1024] @ [1024,3072] + bias (tf32 + ldmatrix)
    gemm_tf32<<<dim3(3 * H_ / 128, MROWS_ / 128), 256>>>(hs, Wa, ba, qkv,
                                                         MROWS_, 3 * H_, H_);

    // 2) split + QK layernorm (Q,K only; V read in-place by attention)
    {
        int warps = 2 * LN_ROWS_;
        int blocks = (warps * 32 + 255) / 256;
        qkv_split_ln<<<blocks, 256>>>(qkv, qg, qb, kg, kb, qh, kh);
    }

    // 3) causal flash attention (tf32 tensor cores, V direct from qkv)
    flash_attn_tc<<<dim3(S_ / 64, B_ * NH_), 128>>>(qh, kh, qkv, ctx);

    // 4) output projection: [4096,1024] @ [1024,1024] + bias
    gemm_tf32<<<dim3(H_ / 128, MROWS_ / 128), 256>>>(ctx, Wp, bp, out,
                                                     MROWS_, H_, H_);
}

// round 6
// speedup vs baseline: 1.1594x; 1.1594x over previous
#include <cuda_runtime.h>
#include <cuda_bf16.h>
#include <math_constants.h>
#include <cstdint>

// Problem constants
#define B_  2
#define S_  2048
#define H_  1024
#define NH_ 16
#define HD_ 64
#define MROWS_ (B_ * S_)          // 4096
#define LN_ROWS_ (B_ * S_ * NH_)  // 65536

// Scratch (device globals — allocation-free rule)
__device__ float g_qkv[(size_t)MROWS_ * 3 * H_];  // [4096, 3072]
__device__ float g_qh [(size_t)MROWS_ * H_];      // [B*NH, S, HD]
__device__ float g_kh [(size_t)MROWS_ * H_];
__device__ float g_vh [(size_t)MROWS_ * H_];
__device__ float g_ctx[(size_t)MROWS_ * H_];      // [B, S, H]

// ---------------------------------------------------------------------------
// tf32 / ldmatrix helpers
// ---------------------------------------------------------------------------
__device__ __forceinline__ float tf32r(float x) {
    float y;
    asm("cvt.rna.tf32.f32 %0, %1;" : "=f"(y) : "f"(x));
    return y;
}

__device__ __forceinline__ void mma_tf32(float c[4], const uint32_t a[4],
                                         const uint32_t b[2]) {
    asm volatile(
        "mma.sync.aligned.m16n8k8.row.col.f32.tf32.tf32.f32 "
        "{%0,%1,%2,%3}, {%4,%5,%6,%7}, {%8,%9}, {%0,%1,%2,%3};"
        : "+f"(c[0]), "+f"(c[1]), "+f"(c[2]), "+f"(c[3])
        : "r"(a[0]), "r"(a[1]), "r"(a[2]), "r"(a[3]), "r"(b[0]), "r"(b[1]));
}

__device__ __forceinline__ void ldsm_x4(uint32_t r[4], uint32_t addr) {
    asm volatile("ldmatrix.sync.aligned.m8n8.x4.shared.b16 {%0,%1,%2,%3}, [%4];"
                 : "=r"(r[0]), "=r"(r[1]), "=r"(r[2]), "=r"(r[3]) : "r"(addr));
}

__device__ __forceinline__ void ldsm_x2(uint32_t r[2], uint32_t addr) {
    asm volatile("ldmatrix.sync.aligned.m8n8.x2.shared.b16 {%0,%1}, [%2];"
                 : "=r"(r[0]), "=r"(r[1]) : "r"(addr));
}

// ---------------------------------------------------------------------------
// TF32 tensor-core GEMM (unchanged from R4): 128x128 tile, BK=16 double-buf,
// ldmatrix fragment loads, conflict-free 20-float row strides.
// ---------------------------------------------------------------------------
#define AP 20

__global__ __launch_bounds__(256, 2) void gemm_tf32(
    const float* __restrict__ A, const float* __restrict__ Bm,
    const float* __restrict__ bias, float* __restrict__ C,
    int M, int N, int K)
{
    __shared__ float As2[2][128][AP];
    __shared__ float Bsn[2][128][AP];

    const int tid  = threadIdx.x;
    const int lane = tid & 31;
    const int warp = tid >> 5;
    const int wm = (warp & 1) * 64;
    const int wn = (warp >> 1) * 32;
    const int gid = lane >> 2;
    const int tig = lane & 3;
    const int brow = blockIdx.y * 128;
    const int bcol = blockIdx.x * 128;

    const int aRow = tid >> 2;
    const int aCol = (tid & 3) * 4;
    const float* Aptr  = A + (size_t)(brow + aRow) * K + aCol;
    const float* Aptr2 = Aptr + (size_t)64 * K;

    const int bN = lane + 32 * (warp & 3);
    const int bK = 8 * (warp >> 2);
    const float* Bptr = Bm + (size_t)bK * N + bcol + bN;

    const int lrowA = (((lane >> 3) & 1) * 8) + (lane & 7);
    const int lcolA = (lane >> 4) * 4;
    const int lrowB = lane & 7;
    const int lcolB = ((lane >> 3) & 1) * 4;

    float c[4][4][4];
#pragma unroll
    for (int i = 0; i < 4; i++)
#pragma unroll
        for (int j = 0; j < 4; j++)
#pragma unroll
            for (int r = 0; r < 4; r++) c[i][j][r] = 0.f;

    float4 av0, av1;
    float bv[8];

    av0 = *(const float4*)(Aptr);
    av1 = *(const float4*)(Aptr2);
#pragma unroll
    for (int j = 0; j < 8; j++) bv[j] = Bptr[(size_t)j * N];
    {
        float4 a0 = make_float4(tf32r(av0.x), tf32r(av0.y), tf32r(av0.z), tf32r(av0.w));
        float4 a1 = make_float4(tf32r(av1.x), tf32r(av1.y), tf32r(av1.z), tf32r(av1.w));
        *(float4*)&As2[0][aRow][aCol]      = a0;
        *(float4*)&As2[0][aRow + 64][aCol] = a1;
        float4 b0 = make_float4(tf32r(bv[0]), tf32r(bv[1]), tf32r(bv[2]), tf32r(bv[3]));
        float4 b1 = make_float4(tf32r(bv[4]), tf32r(bv[5]), tf32r(bv[6]), tf32r(bv[7]));
        *(float4*)&Bsn[0][bN][bK]     = b0;
        *(float4*)&Bsn[0][bN][bK + 4] = b1;
    }
    __syncthreads();

    const uint32_t smemA = (uint32_t)__cvta_generic_to_shared(&As2[0][0][0]);
    const uint32_t smemB = (uint32_t)__cvta_generic_to_shared(&Bsn[0][0][0]);
    const uint32_t bufStride = 128 * AP * 4;
    const uint32_t aOff = ((uint32_t)(wm + lrowA) * AP + lcolA) * 4;
    const uint32_t bOff = ((uint32_t)(wn + lrowB) * AP + lcolB) * 4;

    const int iters = K / 16;
    for (int t = 0; t < iters; t++) {
        const int buf = t & 1;
        if (t + 1 < iters) {
            const int k0 = (t + 1) * 16;
            av0 = *(const float4*)(Aptr + k0);
            av1 = *(const float4*)(Aptr2 + k0);
#pragma unroll
            for (int j = 0; j < 8; j++) bv[j] = Bptr[(size_t)(k0 + j) * N];
        }

        const uint32_t aBase = smemA + buf * bufStride + aOff;
        const uint32_t bBase = smemB + buf * bufStride + bOff;
#pragma unroll
        for (int ks = 0; ks < 2; ks++) {
            uint32_t af[4][4], bf[4][2];
#pragma unroll
            for (int mt = 0; mt < 4; mt++)
                ldsm_x4(af[mt], aBase + (uint32_t)(mt * 16 * AP + ks * 8) * 4);
#pragma unroll
            for (int nt = 0; nt < 4; nt++)
                ldsm_x2(bf[nt], bBase + (uint32_t)(nt * 8 * AP + ks * 8) * 4);
#pragma unroll
            for (int mt = 0; mt < 4; mt++)
#pragma unroll
                for (int nt = 0; nt < 4; nt++)
                    mma_tf32(c[mt][nt], af[mt], bf[nt]);
        }

        if (t + 1 < iters) {
            const int nb = (t + 1) & 1;
            float4 a0 = make_float4(tf32r(av0.x), tf32r(av0.y), tf32r(av0.z), tf32r(av0.w));
            float4 a1 = make_float4(tf32r(av1.x), tf32r(av1.y), tf32r(av1.z), tf32r(av1.w));
            *(float4*)&As2[nb][aRow][aCol]      = a0;
            *(float4*)&As2[nb][aRow + 64][aCol] = a1;
            float4 b0 = make_float4(tf32r(bv[0]), tf32r(bv[1]), tf32r(bv[2]), tf32r(bv[3]));
            float4 b1 = make_float4(tf32r(bv[4]), tf32r(bv[5]), tf32r(bv[6]), tf32r(bv[7]));
            *(float4*)&Bsn[nb][bN][bK]     = b0;
            *(float4*)&Bsn[nb][bN][bK + 4] = b1;
            __syncthreads();
        }
    }

#pragma unroll
    for (int mt = 0; mt < 4; mt++) {
        const int row = brow + wm + mt * 16 + gid;
#pragma unroll
        for (int nt = 0; nt < 4; nt++) {
            const int col = bcol + wn + nt * 8 + tig * 2;
            const float b0 = bias[col], b1 = bias[col + 1];
            float2 o0 = make_float2(c[mt][nt][0] + b0, c[mt][nt][1] + b1);
            float2 o1 = make_float2(c[mt][nt][2] + b0, c[mt][nt][3] + b1);
            *(float2*)&C[(size_t)row * N + col]       = o0;
            *(float2*)&C[(size_t)(row + 8) * N + col] = o1;
        }
    }
}

// ---------------------------------------------------------------------------
// Split QKV + per-head LayerNorm on Q,K; contiguous copy for V (restored).
// ---------------------------------------------------------------------------
__global__ __launch_bounds__(256) void qkv_split_ln(
    const float* __restrict__ qkv,
    const float* __restrict__ qg, const float* __restrict__ qb,
    const float* __restrict__ kg, const float* __restrict__ kb,
    float* __restrict__ qh, float* __restrict__ kh, float* __restrict__ vh)
{
    int w = (blockIdx.x * blockDim.x + threadIdx.x) >> 5;
    int lane = threadIdx.x & 31;
    int t = w / LN_ROWS_;      // 0:q 1:k 2:v
    int row = w - t * LN_ROWS_;
    if (t >= 3) return;

    int b = row / (S_ * NH_);
    int rem = row - b * (S_ * NH_);
    int s = rem / NH_;
    int n = rem - s * NH_;

    const float* src = qkv + (size_t)(b * S_ + s) * (3 * H_) + t * H_ + n * HD_;
    float* dst = (t == 0 ? qh : (t == 1 ? kh : vh)) +
                 ((size_t)(b * NH_ + n) * S_ + s) * HD_;

    float x0 = src[lane];
    float x1 = src[lane + 32];
    if (t == 2) { dst[lane] = x0; dst[lane + 32] = x1; return; }

    float s1 = x0 + x1;
    float s2 = x0 * x0 + x1 * x1;
#pragma unroll
    for (int o = 16; o > 0; o >>= 1) {
        s1 += __shfl_xor_sync(0xffffffffu, s1, o);
        s2 += __shfl_xor_sync(0xffffffffu, s2, o);
    }
    float mu  = s1 * (1.0f / HD_);
    float var = s2 * (1.0f / HD_) - mu * mu;
    float inv = rsqrtf(var + 1e-5f);

    const float* g  = (t == 0) ? qg : kg;
    const float* be = (t == 0) ? qb : kb;
    dst[lane]      = (x0 - mu) * inv * g[lane]      + be[lane];
    dst[lane + 32] = (x1 - mu) * inv * g[lane + 32] + be[lane + 32];
}

// ---------------------------------------------------------------------------
// Causal flash attention, TF32 tensor cores.
// CTA = 256 thr (8 warps) per 128-row Q tile; warp w owns rows [w*16, w*16+16).
// K/V tiles of 32 keys amortized over 2x compute vs R3.
// ---------------------------------------------------------------------------
__global__ __launch_bounds__(256, 2) void flash_attn_tc(
    const float* __restrict__ qh, const float* __restrict__ kh,
    const float* __restrict__ vh, float* __restrict__ ctx)
{
    __shared__ float Ks[32][68];    // QK B-frag conflict-free
    __shared__ float Vs[32][72];    // PV B-frag conflict-free
    __shared__ float Ps[128][36];   // P + Q staging

    const int bh  = blockIdx.y;     // 0..31
    const int qt  = blockIdx.x;     // 0..15
    const int tid = threadIdx.x;
    const int lane = tid & 31;
    const int w    = tid >> 5;      // 0..7
    const int gid  = lane >> 2;
    const int tig  = lane & 3;
    const int qbase = qt * 128;
    const int wrow  = w * 16;

    const float* Q  = qh + (size_t)bh * S_ * HD_ + (size_t)qbase * HD_;
    const float* Kp = kh + (size_t)bh * S_ * HD_;
    const float* Vp = vh + (size_t)bh * S_ * HD_;

    // --- Load Q fragments (register-resident), staged through Ps ---
    uint32_t qa[8][4];
#pragma unroll
    for (int h = 0; h < 2; h++) {
        for (int i = tid; i < 128 * 8; i += 256) {
            int r = i >> 3, c4 = (i & 7) * 4;
            float4 v = *(const float4*)&Q[r * HD_ + h * 32 + c4];
            Ps[r][c4 + 0] = tf32r(v.x);
            Ps[r][c4 + 1] = tf32r(v.y);
            Ps[r][c4 + 2] = tf32r(v.z);
            Ps[r][c4 + 3] = tf32r(v.w);
        }
        __syncthreads();
#pragma unroll
        for (int ks = 0; ks < 4; ks++) {
            qa[h * 4 + ks][0] = __float_as_uint(Ps[wrow + gid][ks * 8 + tig]);
            qa[h * 4 + ks][1] = __float_as_uint(Ps[wrow + gid + 8][ks * 8 + tig]);
            qa[h * 4 + ks][2] = __float_as_uint(Ps[wrow + gid][ks * 8 + tig + 4]);
            qa[h * 4 + ks][3] = __float_as_uint(Ps[wrow + gid + 8][ks * 8 + tig + 4]);
        }
        __syncthreads();
    }

    float o[8][4];
#pragma unroll
    for (int i = 0; i < 8; i++)
#pragma unroll
        for (int j = 0; j < 4; j++) o[i][j] = 0.f;
    float m0 = -CUDART_INF_F, m1 = -CUDART_INF_F;
    float l0 = 0.f, l1 = 0.f;

    const int r0g = qbase + wrow + gid;
    const int r1g = r0g + 8;
    const int rmaxw = qbase + wrow + 15;
    const int nkt = (qt + 1) * 4;     // 32-key tiles to causal bound
    const float scl = 0.125f;

    for (int kt = 0; kt < nkt; kt++) {
        const int kbase = kt * 32;
        for (int i = tid; i < 32 * 16; i += 256) {
            int r = i >> 4, c4 = (i & 15) * 4;
            float4 kv = *(const float4*)&Kp[(size_t)(kbase + r) * HD_ + c4];
            Ks[r][c4 + 0] = tf32r(kv.x); Ks[r][c4 + 1] = tf32r(kv.y);
            Ks[r][c4 + 2] = tf32r(kv.z); Ks[r][c4 + 3] = tf32r(kv.w);
            float4 vv = *(const float4*)&Vp[(size_t)(kbase + r) * HD_ + c4];
            Vs[r][c4 + 0] = tf32r(vv.x); Vs[r][c4 + 1] = tf32r(vv.y);
            Vs[r][c4 + 2] = tf32r(vv.z); Vs[r][c4 + 3] = tf32r(vv.w);
        }
        __syncthreads();

        if (kbase <= rmaxw) {
            float s[4][4];
#pragma unroll
            for (int nt = 0; nt < 4; nt++)
#pragma unroll
                for (int j = 0; j < 4; j++) s[nt][j] = 0.f;
#pragma unroll
            for (int nt = 0; nt < 4; nt++) {
#pragma unroll
                for (int ks = 0; ks < 8; ks++) {
                    uint32_t b[2];
                    b[0] = __float_as_uint(Ks[nt * 8 + gid][ks * 8 + tig]);
                    b[1] = __float_as_uint(Ks[nt * 8 + gid][ks * 8 + tig + 4]);
                    mma_tf32(s[nt], qa[ks], b);
                }
            }

            if (kbase + 31 <= qbase + wrow) {
#pragma unroll
                for (int nt = 0; nt < 4; nt++)
#pragma unroll
                    for (int j = 0; j < 4; j++) s[nt][j] *= scl;
            } else {
#pragma unroll
                for (int nt = 0; nt < 4; nt++) {
                    int c0 = kbase + nt * 8 + tig * 2;
                    s[nt][0] = (c0     <= r0g) ? s[nt][0] * scl : -CUDART_INF_F;
                    s[nt][1] = (c0 + 1 <= r0g) ? s[nt][1] * scl : -CUDART_INF_F;
                    s[nt][2] = (c0     <= r1g) ? s[nt][2] * scl : -CUDART_INF_F;
                    s[nt][3] = (c0 + 1 <= r1g) ? s[nt][3] * scl : -CUDART_INF_F;
                }
            }

            float mt0 = fmaxf(fmaxf(s[0][0], s[0][1]), fmaxf(s[1][0], s[1][1]));
            mt0 = fmaxf(mt0, fmaxf(fmaxf(s[2][0], s[2][1]), fmaxf(s[3][0], s[3][1])));
            float mt1 = fmaxf(fmaxf(s[0][2], s[0][3]), fmaxf(s[1][2], s[1][3]));
            mt1 = fmaxf(mt1, fmaxf(fmaxf(s[2][2], s[2][3]), fmaxf(s[3][2], s[3][3])));
            mt0 = fmaxf(mt0, __shfl_xor_sync(0xffffffffu, mt0, 1));
            mt0 = fmaxf(mt0, __shfl_xor_sync(0xffffffffu, mt0, 2));
            mt1 = fmaxf(mt1, __shfl_xor_sync(0xffffffffu, mt1, 1));
            mt1 = fmaxf(mt1, __shfl_xor_sync(0xffffffffu, mt1, 2));

            float mn0 = fmaxf(m0, mt0), mn1 = fmaxf(m1, mt1);
            float a0 = __expf(m0 - mn0), a1 = __expf(m1 - mn1);
            m0 = mn0; m1 = mn1;

            float ps0 = 0.f, ps1 = 0.f;
#pragma unroll
            for (int nt = 0; nt < 4; nt++) {
                float p0 = tf32r(__expf(s[nt][0] - mn0));
                float p1 = tf32r(__expf(s[nt][1] - mn0));
                float p2 = tf32r(__expf(s[nt][2] - mn1));
                float p3 = tf32r(__expf(s[nt][3] - mn1));
                ps0 += p0 + p1;
                ps1 += p2 + p3;
                Ps[wrow + gid][nt * 8 + tig * 2 + 0]     = p0;
                Ps[wrow + gid][nt * 8 + tig * 2 + 1]     = p1;
                Ps[wrow + gid + 8][nt * 8 + tig * 2 + 0] = p2;
                Ps[wrow + gid + 8][nt * 8 + tig * 2 + 1] = p3;
            }
            ps0 += __shfl_xor_sync(0xffffffffu, ps0, 1);
            ps0 += __shfl_xor_sync(0xffffffffu, ps0, 2);
            ps1 += __shfl_xor_sync(0xffffffffu, ps1, 1);
            ps1 += __shfl_xor_sync(0xffffffffu, ps1, 2);
            l0 = l0 * a0 + ps0;
            l1 = l1 * a1 + ps1;

#pragma unroll
            for (int nt = 0; nt < 8; nt++) {
                o[nt][0] *= a0; o[nt][1] *= a0;
                o[nt][2] *= a1; o[nt][3] *= a1;
            }

            uint32_t pa[4][4];
#pragma unroll
            for (int ks = 0; ks < 4; ks++) {
                pa[ks][0] = __float_as_uint(Ps[wrow + gid][ks * 8 + tig]);
                pa[ks][1] = __float_as_uint(Ps[wrow + gid + 8][ks * 8 + tig]);
                pa[ks][2] = __float_as_uint(Ps[wrow + gid][ks * 8 + tig + 4]);
                pa[ks][3] = __float_as_uint(Ps[wrow + gid + 8][ks * 8 + tig + 4]);
            }
#pragma unroll
            for (int nt = 0; nt < 8; nt++) {
#pragma unroll
                for (int ks = 0; ks < 4; ks++) {
                    uint32_t b[2];
                    b[0] = __float_as_uint(Vs[ks * 8 + tig][nt * 8 + gid]);
                    b[1] = __float_as_uint(Vs[ks * 8 + tig + 4][nt * 8 + gid]);
                    mma_tf32(o[nt], pa[ks], b);
                }
            }
        }
        __syncthreads();
    }

    const int bb = bh >> 4;
    const int nh = bh & 15;
    const float inv0 = 1.0f / l0;
    const float inv1 = 1.0f / l1;
    float* orow0 = ctx + (size_t)(bb * S_ + r0g) * H_ + nh * HD_;
    float* orow1 = ctx + (size_t)(bb * S_ + r1g) * H_ + nh * HD_;
#pragma unroll
    for (int nt = 0; nt < 8; nt++) {
        int col = nt * 8 + tig * 2;
        *(float2*)&orow0[col] = make_float2(o[nt][0] * inv0, o[nt][1] * inv0);
        *(float2*)&orow1[col] = make_float2(o[nt][2] * inv1, o[nt][3] * inv1);
    }
}

// ---------------------------------------------------------------------------
extern "C" void kernel_launch(void* const* d_in, const int* in_sizes, int n_in,
                              void* d_out, int out_size)
{
    const float* hs = (const float*)d_in[0];
    const float* Wa = (const float*)d_in[1];
    const float* ba = (const float*)d_in[2];
    const float* Wp = (const float*)d_in[3];
    const float* bp = (const float*)d_in[4];
    const float* qg = (const float*)d_in[5];
    const float* qb = (const float*)d_in[6];
    const float* kg = (const float*)d_in[7];
    const float* kb = (const float*)d_in[8];
    float* out = (float*)d_out;

    float *qkv, *qh, *kh, *vh, *ctx;
    cudaGetSymbolAddress((void**)&qkv, g_qkv);
    cudaGetSymbolAddress((void**)&qh,  g_qh);
    cudaGetSymbolAddress((void**)&kh,  g_kh);
    cudaGetSymbolAddress((void**)&vh,  g_vh);
    cudaGetSymbolAddress((void**)&ctx, g_ctx);

    // 1) QKV GEMM: [4096,1024] @ [1024,3072] + bias (tf32 + ldmatrix)
    gemm_tf32<<<dim3(3 * H_ / 128, MROWS_ / 128), 256>>>(hs, Wa, ba, qkv,
                                                         MROWS_, 3 * H_, H_);

    // 2) split + QK layernorm + V copy
    {
        int warps = 3 * LN_ROWS_;
        int blocks = (warps * 32 + 255) / 256;
        qkv_split_ln<<<blocks, 256>>>(qkv, qg, qb, kg, kb, qh, kh, vh);
    }

    // 3) causal flash attention (tf32, 128-row Q tiles)
    flash_attn_tc<<<dim3(S_ / 128, B_ * NH_), 256>>>(qh, kh, vh, ctx);

    // 4) output projection: [4096,1024] @ [1024,1024] + bias
    gemm_tf32<<<dim3(H_ / 128, MROWS_ / 128), 256>>>(ctx, Wp, bp, out,
                                                     MROWS_, H_, H_);
}

// round 7
// speedup vs baseline: 1.9660x; 1.6957x over previous
#include <cuda_runtime.h>
#include <cuda_fp16.h>
#include <math_constants.h>
#include <cstdint>

// Problem constants
#define B_  2
#define S_  2048
#define H_  1024
#define NH_ 16
#define HD_ 64
#define MROWS_ (B_ * S_)          // 4096
#define LN_ROWS_ (B_ * S_ * NH_)  // 65536

// Scratch (device globals — allocation-free rule)
__device__ float  g_qkv[(size_t)MROWS_ * 3 * H_];  // [4096, 3072] fp32
__device__ __half g_qh [(size_t)MROWS_ * H_];      // [B*NH, S, HD] fp16
__device__ __half g_kh [(size_t)MROWS_ * H_];
__device__ __half g_vh [(size_t)MROWS_ * H_];
__device__ float  g_ctx[(size_t)MROWS_ * H_];      // [B, S, H] fp32

// ---------------------------------------------------------------------------
// fp16 helpers
// ---------------------------------------------------------------------------
__device__ __forceinline__ uint32_t h2r(float lo, float hi) {
    __half2 h = __floats2half2_rn(lo, hi);
    return *reinterpret_cast<uint32_t*>(&h);
}

__device__ __forceinline__ void mma_fp16(float c[4], const uint32_t a[4],
                                         const uint32_t b[2]) {
    asm volatile(
        "mma.sync.aligned.m16n8k16.row.col.f32.f16.f16.f32 "
        "{%0,%1,%2,%3}, {%4,%5,%6,%7}, {%8,%9}, {%0,%1,%2,%3};"
        : "+f"(c[0]), "+f"(c[1]), "+f"(c[2]), "+f"(c[3])
        : "r"(a[0]), "r"(a[1]), "r"(a[2]), "r"(a[3]), "r"(b[0]), "r"(b[1]));
}

__device__ __forceinline__ void ldsm_x4(uint32_t r[4], uint32_t addr) {
    asm volatile("ldmatrix.sync.aligned.m8n8.x4.shared.b16 {%0,%1,%2,%3}, [%4];"
                 : "=r"(r[0]), "=r"(r[1]), "=r"(r[2]), "=r"(r[3]) : "r"(addr));
}

__device__ __forceinline__ void ldsm_x2(uint32_t r[2], uint32_t addr) {
    asm volatile("ldmatrix.sync.aligned.m8n8.x2.shared.b16 {%0,%1}, [%2];"
                 : "=r"(r[0]), "=r"(r[1]) : "r"(addr));
}

__device__ __forceinline__ void ldsm_x2_t(uint32_t r[2], uint32_t addr) {
    asm volatile("ldmatrix.sync.aligned.m8n8.x2.trans.shared.b16 {%0,%1}, [%2];"
                 : "=r"(r[0]), "=r"(r[1]) : "r"(addr));
}

// ---------------------------------------------------------------------------
// FP16 tensor-core GEMM: C[M,N] = A[M,K] @ B[K,N] + bias[N]  (fp32 in/out)
// 128x128 tile, BK=16 double-buffered. 8 warps of 64x32 (4x4 m16n8k16).
//   As[m][k]  half, row stride 24 (48B) -> ldmatrix rows conflict-free
//   Bs[k][n]  half, row stride 136 (272B) -> trans-ldmatrix rows conflict-free
// ---------------------------------------------------------------------------
#define AH 24
#define BH 136

__global__ __launch_bounds__(256, 2) void gemm_fp16(
    const float* __restrict__ A, const float* __restrict__ Bm,
    const float* __restrict__ bias, float* __restrict__ C,
    int M, int N, int K)
{
    __shared__ __half As[2][128][AH];
    __shared__ __half Bs[2][16][BH];

    const int tid  = threadIdx.x;
    const int lane = tid & 31;
    const int warp = tid >> 5;
    const int wm = (warp & 1) * 64;
    const int wn = (warp >> 1) * 32;
    const int gid = lane >> 2;
    const int tig = lane & 3;
    const int brow = blockIdx.y * 128;
    const int bcol = blockIdx.x * 128;

    // A: 128x16 fp32 tile, 2 float4/thread
    const int aRow = tid >> 2;        // 0..63 (+64)
    const int aCol = (tid & 3) * 4;   // k offset 0,4,8,12
    const float* Aptr  = A + (size_t)(brow + aRow) * K + aCol;
    const float* Aptr2 = Aptr + (size_t)64 * K;

    // B: 16x128 fp32 tile, 2 float4/thread (rows k, n-contiguous)
    const int bRow = tid >> 5;        // 0..7 (+8)
    const int bCol = (tid & 31) * 4;  // n offset
    const float* Bptr  = Bm + (size_t)bRow * N + bcol + bCol;
    const float* Bptr2 = Bptr + (size_t)8 * N;

    float c[4][4][4];
#pragma unroll
    for (int i = 0; i < 4; i++)
#pragma unroll
        for (int j = 0; j < 4; j++)
#pragma unroll
            for (int r = 0; r < 4; r++) c[i][j][r] = 0.f;

    float4 av0, av1, bv0, bv1;

    av0 = *(const float4*)(Aptr);
    av1 = *(const float4*)(Aptr2);
    bv0 = *(const float4*)(Bptr);
    bv1 = *(const float4*)(Bptr2);
    {
        *(__half2*)&As[0][aRow][aCol]          = __floats2half2_rn(av0.x, av0.y);
        *(__half2*)&As[0][aRow][aCol + 2]      = __floats2half2_rn(av0.z, av0.w);
        *(__half2*)&As[0][aRow + 64][aCol]     = __floats2half2_rn(av1.x, av1.y);
        *(__half2*)&As[0][aRow + 64][aCol + 2] = __floats2half2_rn(av1.z, av1.w);
        *(__half2*)&Bs[0][bRow][bCol]          = __floats2half2_rn(bv0.x, bv0.y);
        *(__half2*)&Bs[0][bRow][bCol + 2]      = __floats2half2_rn(bv0.z, bv0.w);
        *(__half2*)&Bs[0][bRow + 8][bCol]      = __floats2half2_rn(bv1.x, bv1.y);
        *(__half2*)&Bs[0][bRow + 8][bCol + 2]  = __floats2half2_rn(bv1.z, bv1.w);
    }
    __syncthreads();

    const uint32_t smemA = (uint32_t)__cvta_generic_to_shared(&As[0][0][0]);
    const uint32_t smemB = (uint32_t)__cvta_generic_to_shared(&Bs[0][0][0]);
    const uint32_t ABUF = 128 * AH * 2;
    const uint32_t BBUF = 16 * BH * 2;
    const int l8  = lane & 7;
    const int h8  = (lane >> 3) & 1;
    const int h16 = (lane >> 4) & 1;
    // A frag addr: row = wm + l8 + h8*8 (+mt*16), col halfs = h16*8
    const uint32_t aOff = ((uint32_t)(wm + l8 + h8 * 8) * AH + h16 * 8) * 2;
    // B frag addr (trans): row k = l8 + h8*8, col halfs = wn + nt*8
    const uint32_t bOff = ((uint32_t)(l8 + h8 * 8) * BH + wn) * 2;

    const int iters = K / 16;
    for (int t = 0; t < iters; t++) {
        const int buf = t & 1;
        if (t + 1 < iters) {
            const int k0 = (t + 1) * 16;
            av0 = *(const float4*)(Aptr + k0);
            av1 = *(const float4*)(Aptr2 + k0);
            bv0 = *(const float4*)(Bptr + (size_t)k0 * N);
            bv1 = *(const float4*)(Bptr2 + (size_t)k0 * N);
        }

        const uint32_t aBase = smemA + buf * ABUF + aOff;
        const uint32_t bBase = smemB + buf * BBUF + bOff;
        uint32_t af[4][4], bf[4][2];
#pragma unroll
        for (int mt = 0; mt < 4; mt++)
            ldsm_x4(af[mt], aBase + (uint32_t)(mt * 16 * AH) * 2);
#pragma unroll
        for (int nt = 0; nt < 4; nt++)
            ldsm_x2_t(bf[nt], bBase + (uint32_t)(nt * 8) * 2);
#pragma unroll
        for (int mt = 0; mt < 4; mt++)
#pragma unroll
            for (int nt = 0; nt < 4; nt++)
                mma_fp16(c[mt][nt], af[mt], bf[nt]);

        if (t + 1 < iters) {
            const int nb = (t + 1) & 1;
            *(__half2*)&As[nb][aRow][aCol]          = __floats2half2_rn(av0.x, av0.y);
            *(__half2*)&As[nb][aRow][aCol + 2]      = __floats2half2_rn(av0.z, av0.w);
            *(__half2*)&As[nb][aRow + 64][aCol]     = __floats2half2_rn(av1.x, av1.y);
            *(__half2*)&As[nb][aRow + 64][aCol + 2] = __floats2half2_rn(av1.z, av1.w);
            *(__half2*)&Bs[nb][bRow][bCol]          = __floats2half2_rn(bv0.x, bv0.y);
            *(__half2*)&Bs[nb][bRow][bCol + 2]      = __floats2half2_rn(bv0.z, bv0.w);
            *(__half2*)&Bs[nb][bRow + 8][bCol]      = __floats2half2_rn(bv1.x, bv1.y);
            *(__half2*)&Bs[nb][bRow + 8][bCol + 2]  = __floats2half2_rn(bv1.z, bv1.w);
            __syncthreads();
        }
    }

    // epilogue: bias add + fp32 store
#pragma unroll
    for (int mt = 0; mt < 4; mt++) {
        const int row = brow + wm + mt * 16 + gid;
#pragma unroll
        for (int nt = 0; nt < 4; nt++) {
            const int col = bcol + wn + nt * 8 + tig * 2;
            const float b0 = bias[col], b1 = bias[col + 1];
            float2 o0 = make_float2(c[mt][nt][0] + b0, c[mt][nt][1] + b1);
            float2 o1 = make_float2(c[mt][nt][2] + b0, c[mt][nt][3] + b1);
            *(float2*)&C[(size_t)row * N + col]       = o0;
            *(float2*)&C[(size_t)(row + 8) * N + col] = o1;
        }
    }
}

// ---------------------------------------------------------------------------
// Split QKV + per-head LayerNorm on Q,K; copy V. Outputs fp16 head-major.
// ---------------------------------------------------------------------------
__global__ __launch_bounds__(256) void qkv_split_ln(
    const float* __restrict__ qkv,
    const float* __restrict__ qg, const float* __restrict__ qb,
    const float* __restrict__ kg, const float* __restrict__ kb,
    __half* __restrict__ qh, __half* __restrict__ kh, __half* __restrict__ vh)
{
    int w = (blockIdx.x * blockDim.x + threadIdx.x) >> 5;
    int lane = threadIdx.x & 31;
    int t = w / LN_ROWS_;      // 0:q 1:k 2:v
    int row = w - t * LN_ROWS_;
    if (t >= 3) return;

    int b = row / (S_ * NH_);
    int rem = row - b * (S_ * NH_);
    int s = rem / NH_;
    int n = rem - s * NH_;

    const float* src = qkv + (size_t)(b * S_ + s) * (3 * H_) + t * H_ + n * HD_;
    __half* dst = (t == 0 ? qh : (t == 1 ? kh : vh)) +
                  ((size_t)(b * NH_ + n) * S_ + s) * HD_;

    float x0 = src[lane];
    float x1 = src[lane + 32];
    if (t == 2) {
        dst[lane]      = __float2half_rn(x0);
        dst[lane + 32] = __float2half_rn(x1);
        return;
    }

    float s1 = x0 + x1;
    float s2 = x0 * x0 + x1 * x1;
#pragma unroll
    for (int o = 16; o > 0; o >>= 1) {
        s1 += __shfl_xor_sync(0xffffffffu, s1, o);
        s2 += __shfl_xor_sync(0xffffffffu, s2, o);
    }
    float mu  = s1 * (1.0f / HD_);
    float var = s2 * (1.0f / HD_) - mu * mu;
    float inv = rsqrtf(var + 1e-5f);

    const float* g  = (t == 0) ? qg : kg;
    const float* be = (t == 0) ? qb : kb;
    dst[lane]      = __float2half_rn((x0 - mu) * inv * g[lane]      + be[lane]);
    dst[lane + 32] = __float2half_rn((x1 - mu) * inv * g[lane + 32] + be[lane + 32]);
}

// ---------------------------------------------------------------------------
// Causal flash attention, fp16 tensor cores.
// CTA = 256 thr (8 warps) per 128-row Q tile; warp w owns 16 rows.
// K/V tiles of 32 keys. P stays in registers (QK C-frag == PV A-frag).
// ---------------------------------------------------------------------------
#define QST 72
#define KST 72
#define VST 72

__global__ __launch_bounds__(256, 2) void flash_attn_fp16(
    const __half* __restrict__ qh, const __half* __restrict__ kh,
    const __half* __restrict__ vh, float* __restrict__ ctx)
{
    __shared__ __half Qs[128][QST];
    __shared__ __half Ks[32][KST];
    __shared__ __half Vs[32][VST];

    const int bh  = blockIdx.y;     // 0..31
    const int qt  = blockIdx.x;     // 0..15
    const int tid = threadIdx.x;
    const int lane = tid & 31;
    const int w    = tid >> 5;      // 0..7
    const int gid  = lane >> 2;
    const int tig  = lane & 3;
    const int l8   = lane & 7;
    const int h8   = (lane >> 3) & 1;
    const int h16  = (lane >> 4) & 1;
    const int qbase = qt * 128;
    const int wrow  = w * 16;

    const __half* Q  = qh + (size_t)bh * S_ * HD_ + (size_t)qbase * HD_;
    const __half* Kp = kh + (size_t)bh * S_ * HD_;
    const __half* Vp = vh + (size_t)bh * S_ * HD_;

    // --- Stage Q (fp16 copy) + load register-resident A fragments ---
    for (int i = tid; i < 128 * 8; i += 256) {
        int r = i >> 3, c8 = (i & 7) * 8;
        *(uint4*)&Qs[r][c8] = *(const uint4*)&Q[r * HD_ + c8];
    }
    __syncthreads();

    const uint32_t qsB = (uint32_t)__cvta_generic_to_shared(&Qs[0][0]) +
                         ((uint32_t)(wrow + l8 + h8 * 8) * QST + h16 * 8) * 2;
    uint32_t qa[4][4];
#pragma unroll
    for (int ks = 0; ks < 4; ks++)
        ldsm_x4(qa[ks], qsB + (uint32_t)(ks * 16) * 2);
    __syncthreads();

    const uint32_t ksB = (uint32_t)__cvta_generic_to_shared(&Ks[0][0]) +
                         ((uint32_t)(l8)*KST + h8 * 8) * 2;          // row=key, col k-chunk
    const uint32_t vsB = (uint32_t)__cvta_generic_to_shared(&Vs[0][0]) +
                         ((uint32_t)(l8 + h8 * 8) * VST) * 2;        // row=key (trans)

    float o[8][4];
#pragma unroll
    for (int i = 0; i < 8; i++)
#pragma unroll
        for (int j = 0; j < 4; j++) o[i][j] = 0.f;
    float m0 = -CUDART_INF_F, m1 = -CUDART_INF_F;
    float l0 = 0.f, l1 = 0.f;

    const int r0g = qbase + wrow + gid;
    const int r1g = r0g + 8;
    const int rmaxw = qbase + wrow + 15;
    const int nkt = (qt + 1) * 4;
    const float scl = 0.125f;

    for (int kt = 0; kt < nkt; kt++) {
        const int kbase = kt * 32;
        // Load K,V tiles: 32x64 halfs each, 1 uint4/thread each
        {
            int r = tid >> 3, c8 = (tid & 7) * 8;
            *(uint4*)&Ks[r][c8] = *(const uint4*)&Kp[(size_t)(kbase + r) * HD_ + c8];
            *(uint4*)&Vs[r][c8] = *(const uint4*)&Vp[(size_t)(kbase + r) * HD_ + c8];
        }
        __syncthreads();

        if (kbase <= rmaxw) {
            // --- S = Q @ K^T ---
            float s[4][4];
#pragma unroll
            for (int nt = 0; nt < 4; nt++)
#pragma unroll
                for (int j = 0; j < 4; j++) s[nt][j] = 0.f;
#pragma unroll
            for (int nt = 0; nt < 4; nt++) {
#pragma unroll
                for (int ks = 0; ks < 4; ks++) {
                    uint32_t b[2];
                    ldsm_x2(b, ksB + (uint32_t)(nt * 8 * KST + ks * 16) * 2);
                    mma_fp16(s[nt], qa[ks], b);
                }
            }

            // --- scale + causal mask ---
            if (kbase + 31 <= qbase + wrow) {
#pragma unroll
                for (int nt = 0; nt < 4; nt++)
#pragma unroll
                    for (int j = 0; j < 4; j++) s[nt][j] *= scl;
            } else {
#pragma unroll
                for (int nt = 0; nt < 4; nt++) {
                    int c0 = kbase + nt * 8 + tig * 2;
                    s[nt][0] = (c0     <= r0g) ? s[nt][0] * scl : -CUDART_INF_F;
                    s[nt][1] = (c0 + 1 <= r0g) ? s[nt][1] * scl : -CUDART_INF_F;
                    s[nt][2] = (c0     <= r1g) ? s[nt][2] * scl : -CUDART_INF_F;
                    s[nt][3] = (c0 + 1 <= r1g) ? s[nt][3] * scl : -CUDART_INF_F;
                }
            }

            // --- row max (quad reduce) ---
            float mt0 = fmaxf(fmaxf(s[0][0], s[0][1]), fmaxf(s[1][0], s[1][1]));
            mt0 = fmaxf(mt0, fmaxf(fmaxf(s[2][0], s[2][1]), fmaxf(s[3][0], s[3][1])));
            float mt1 = fmaxf(fmaxf(s[0][2], s[0][3]), fmaxf(s[1][2], s[1][3]));
            mt1 = fmaxf(mt1, fmaxf(fmaxf(s[2][2], s[2][3]), fmaxf(s[3][2], s[3][3])));
            mt0 = fmaxf(mt0, __shfl_xor_sync(0xffffffffu, mt0, 1));
            mt0 = fmaxf(mt0, __shfl_xor_sync(0xffffffffu, mt0, 2));
            mt1 = fmaxf(mt1, __shfl_xor_sync(0xffffffffu, mt1, 1));
            mt1 = fmaxf(mt1, __shfl_xor_sync(0xffffffffu, mt1, 2));

            float mn0 = fmaxf(m0, mt0), mn1 = fmaxf(m1, mt1);
            float a0 = __expf(m0 - mn0), a1 = __expf(m1 - mn1);
            m0 = mn0; m1 = mn1;

            // --- P = exp(S-m); keep in registers as fp16 A-fragments ---
            float p[4][4];
            float ps0 = 0.f, ps1 = 0.f;
#pragma unroll
            for (int nt = 0; nt < 4; nt++) {
                p[nt][0] = __expf(s[nt][0] - mn0);
                p[nt][1] = __expf(s[nt][1] - mn0);
                p[nt][2] = __expf(s[nt][2] - mn1);
                p[nt][3] = __expf(s[nt][3] - mn1);
                ps0 += p[nt][0] + p[nt][1];
                ps1 += p[nt][2] + p[nt][3];
            }
            ps0 += __shfl_xor_sync(0xffffffffu, ps0, 1);
            ps0 += __shfl_xor_sync(0xffffffffu, ps0, 2);
            ps1 += __shfl_xor_sync(0xffffffffu, ps1, 1);
            ps1 += __shfl_xor_sync(0xffffffffu, ps1, 2);
            l0 = l0 * a0 + ps0;
            l1 = l1 * a1 + ps1;

            uint32_t pa[2][4];
#pragma unroll
            for (int ks = 0; ks < 2; ks++) {
                pa[ks][0] = h2r(p[2 * ks][0],     p[2 * ks][1]);
                pa[ks][1] = h2r(p[2 * ks][2],     p[2 * ks][3]);
                pa[ks][2] = h2r(p[2 * ks + 1][0], p[2 * ks + 1][1]);
                pa[ks][3] = h2r(p[2 * ks + 1][2], p[2 * ks + 1][3]);
            }

            // --- rescale O, O += P @ V ---
#pragma unroll
            for (int nt = 0; nt < 8; nt++) {
                o[nt][0] *= a0; o[nt][1] *= a0;
                o[nt][2] *= a1; o[nt][3] *= a1;
            }
#pragma unroll
            for (int nt = 0; nt < 8; nt++) {
#pragma unroll
                for (int ks = 0; ks < 2; ks++) {
                    uint32_t b[2];
                    ldsm_x2_t(b, vsB + (uint32_t)(ks * 16 * VST + nt * 8) * 2);
                    mma_fp16(o[nt], pa[ks], b);
                }
            }
        }
        __syncthreads();
    }

    // --- normalize + write ctx [B,S,H] fp32 ---
    const int bb = bh >> 4;
    const int nh = bh & 15;
    const float inv0 = 1.0f / l0;
    const float inv1 = 1.0f / l1;
    float* orow0 = ctx + (size_t)(bb * S_ + r0g) * H_ + nh * HD_;
    float* orow1 = ctx + (size_t)(bb * S_ + r1g) * H_ + nh * HD_;
#pragma unroll
    for (int nt = 0; nt < 8; nt++) {
        int col = nt * 8 + tig * 2;
        *(float2*)&orow0[col] = make_float2(o[nt][0] * inv0, o[nt][1] * inv0);
        *(float2*)&orow1[col] = make_float2(o[nt][2] * inv1, o[nt][3] * inv1);
    }
}

// ---------------------------------------------------------------------------
extern "C" void kernel_launch(void* const* d_in, const int* in_sizes, int n_in,
                              void* d_out, int out_size)
{
    const float* hs = (const float*)d_in[0];
    const float* Wa = (const float*)d_in[1];
    const float* ba = (const float*)d_in[2];
    const float* Wp = (const float*)d_in[3];
    const float* bp = (const float*)d_in[4];
    const float* qg = (const float*)d_in[5];
    const float* qb = (const float*)d_in[6];
    const float* kg = (const float*)d_in[7];
    const float* kb = (const float*)d_in[8];
    float* out = (float*)d_out;

    float *qkv, *ctx;
    __half *qh, *kh, *vh;
    cudaGetSymbolAddress((void**)&qkv, g_qkv);
    cudaGetSymbolAddress((void**)&qh,  g_qh);
    cudaGetSymbolAddress((void**)&kh,  g_kh);
    cudaGetSymbolAddress((void**)&vh,  g_vh);
    cudaGetSymbolAddress((void**)&ctx, g_ctx);

    // 1) QKV GEMM: [4096,1024] @ [1024,3072] + bias (fp16 tensor cores)
    gemm_fp16<<<dim3(3 * H_ / 128, MROWS_ / 128), 256>>>(hs, Wa, ba, qkv,
                                                         MROWS_, 3 * H_, H_);

    // 2) split + QK layernorm + V copy (fp16 outputs)
    {
        int warps = 3 * LN_ROWS_;
        int blocks = (warps * 32 + 255) / 256;
        qkv_split_ln<<<blocks, 256>>>(qkv, qg, qb, kg, kb, qh, kh, vh);
    }

    // 3) causal flash attention (fp16, 128-row Q tiles, P in registers)
    flash_attn_fp16<<<dim3(S_ / 128, B_ * NH_), 256>>>(qh, kh, vh, ctx);

    // 4) output projection: [4096,1024] @ [1024,1024] + bias
    gemm_fp16<<<dim3(H_ / 128, MROWS_ / 128), 256>>>(ctx, Wp, bp, out,
                                                     MROWS_, H_, H_);
}

// round 8
// speedup vs baseline: 2.1899x; 1.1139x over previous
#include <cuda_runtime.h>
#include <cuda_fp16.h>
#include <math_constants.h>
#include <cstdint>

// Problem constants
#define B_  2
#define S_  2048
#define H_  1024
#define NH_ 16
#define HD_ 64
#define MROWS_ (B_ * S_)          // 4096
#define LN_ROWS_ (B_ * S_ * NH_)  // 65536

// Scratch (device globals — allocation-free rule)
__device__ float  g_qkv[(size_t)MROWS_ * 3 * H_];   // [4096, 3072] fp32
__device__ __half g_hsh[(size_t)MROWS_ * H_];       // hs in fp16
__device__ __half g_wah[(size_t)H_ * 3 * H_];       // W_attn fp16
__device__ __half g_wph[(size_t)H_ * H_];           // W_proj fp16
__device__ __half g_qh [(size_t)MROWS_ * H_];       // [B*NH, S, HD] fp16
__device__ __half g_kh [(size_t)MROWS_ * H_];
__device__ __half g_vh [(size_t)MROWS_ * H_];
__device__ __half g_ctxh[(size_t)MROWS_ * H_];      // [B, S, H] fp16

// ---------------------------------------------------------------------------
// helpers
// ---------------------------------------------------------------------------
__device__ __forceinline__ uint32_t h2r(float lo, float hi) {
    __half2 h = __floats2half2_rn(lo, hi);
    return *reinterpret_cast<uint32_t*>(&h);
}

__device__ __forceinline__ void mma_fp16(float c[4], const uint32_t a[4],
                                         const uint32_t b[2]) {
    asm volatile(
        "mma.sync.aligned.m16n8k16.row.col.f32.f16.f16.f32 "
        "{%0,%1,%2,%3}, {%4,%5,%6,%7}, {%8,%9}, {%0,%1,%2,%3};"
        : "+f"(c[0]), "+f"(c[1]), "+f"(c[2]), "+f"(c[3])
        : "r"(a[0]), "r"(a[1]), "r"(a[2]), "r"(a[3]), "r"(b[0]), "r"(b[1]));
}

__device__ __forceinline__ void ldsm_x4(uint32_t r[4], uint32_t addr) {
    asm volatile("ldmatrix.sync.aligned.m8n8.x4.shared.b16 {%0,%1,%2,%3}, [%4];"
                 : "=r"(r[0]), "=r"(r[1]), "=r"(r[2]), "=r"(r[3]) : "r"(addr));
}

__device__ __forceinline__ void ldsm_x2(uint32_t r[2], uint32_t addr) {
    asm volatile("ldmatrix.sync.aligned.m8n8.x2.shared.b16 {%0,%1}, [%2];"
                 : "=r"(r[0]), "=r"(r[1]) : "r"(addr));
}

__device__ __forceinline__ void ldsm_x2_t(uint32_t r[2], uint32_t addr) {
    asm volatile("ldmatrix.sync.aligned.m8n8.x2.trans.shared.b16 {%0,%1}, [%2];"
                 : "=r"(r[0]), "=r"(r[1]) : "r"(addr));
}

__device__ __forceinline__ void cp16(uint32_t smem, const void* gmem) {
    asm volatile("cp.async.cg.shared.global [%0], [%1], 16;" ::
                 "r"(smem), "l"(gmem));
}
__device__ __forceinline__ void cp_commit() {
    asm volatile("cp.async.commit_group;");
}
template <int N>
__device__ __forceinline__ void cp_wait() {
    asm volatile("cp.async.wait_group %0;" :: "n"(N));
}

// ---------------------------------------------------------------------------
// fp32 -> fp16 conversion (vectorized, n % 4 == 0)
// ---------------------------------------------------------------------------
__global__ __launch_bounds__(256) void f2h(const float4* __restrict__ in,
                                           uint2* __restrict__ out, int n4)
{
    int i = blockIdx.x * blockDim.x + threadIdx.x;
    if (i < n4) {
        float4 v = in[i];
        uint2 o;
        o.x = h2r(v.x, v.y);
        o.y = h2r(v.z, v.w);
        out[i] = o;
    }
}

// ---------------------------------------------------------------------------
// FP16 tensor-core GEMM with cp.async: C[M,N] = A[M,K] @ B[K,N] + bias[N]
// A,B fp16 in gmem; C fp32. 128x128 tile, BK=32, 2-stage cp.async pipeline.
//   As[m][k]  row stride 40 halfs (80B)  -> ldsm conflict-free
//   Bs[k][n]  row stride 136 halfs (272B) -> trans-ldsm conflict-free
// ---------------------------------------------------------------------------
#define AH 40
#define BH 136

__global__ __launch_bounds__(256, 2) void gemm_fp16a(
    const __half* __restrict__ A, const __half* __restrict__ Bm,
    const float* __restrict__ bias, float* __restrict__ C,
    int M, int N, int K)
{
    __shared__ __half As[2][128][AH];
    __shared__ __half Bs[2][32][BH];

    const int tid  = threadIdx.x;
    const int lane = tid & 31;
    const int warp = tid >> 5;
    const int wm = (warp & 1) * 64;
    const int wn = (warp >> 1) * 32;
    const int gid = lane >> 2;
    const int tig = lane & 3;
    const int brow = blockIdx.y * 128;
    const int bcol = blockIdx.x * 128;

    // A tile 128x32 halfs: 2 x 16B per thread
    const int aRow = tid >> 2;          // 0..63 (+64)
    const int aCol = (tid & 3) * 8;     // half offset 0,8,16,24
    const __half* Aptr  = A + (size_t)(brow + aRow) * K + aCol;
    const __half* Aptr2 = Aptr + (size_t)64 * K;

    // B tile 32x128 halfs: 2 x 16B per thread
    const int bRow = tid >> 4;          // 0..15 (+16)
    const int bCol = (tid & 15) * 8;    // half offset 0..120
    const __half* Bptr  = Bm + (size_t)bRow * N + bcol + bCol;
    const __half* Bptr2 = Bptr + (size_t)16 * N;

    const uint32_t asB = (uint32_t)__cvta_generic_to_shared(&As[0][0][0]);
    const uint32_t bsB = (uint32_t)__cvta_generic_to_shared(&Bs[0][0][0]);
    const uint32_t ABUF = 128 * AH * 2;
    const uint32_t BBUF = 32 * BH * 2;
    const uint32_t aSt0 = (uint32_t)(aRow * AH + aCol) * 2;
    const uint32_t aSt1 = (uint32_t)((aRow + 64) * AH + aCol) * 2;
    const uint32_t bSt0 = (uint32_t)(bRow * BH + bCol) * 2;
    const uint32_t bSt1 = (uint32_t)((bRow + 16) * BH + bCol) * 2;

    float c[4][4][4];
#pragma unroll
    for (int i = 0; i < 4; i++)
#pragma unroll
        for (int j = 0; j < 4; j++)
#pragma unroll
            for (int r = 0; r < 4; r++) c[i][j][r] = 0.f;

    // ldsm per-thread coords
    const int l8  = lane & 7;
    const int h8  = (lane >> 3) & 1;
    const int h16 = (lane >> 4) & 1;
    const uint32_t aOff = ((uint32_t)(wm + l8 + h8 * 8) * AH + h16 * 8) * 2;
    const uint32_t bOff = ((uint32_t)(l8 + h8 * 8) * BH + wn) * 2;

    const int iters = K / 32;

    // prologue: issue tile 0
    {
        cp16(asB + aSt0, Aptr);
        cp16(asB + aSt1, Aptr2);
        cp16(bsB + bSt0, Bptr);
        cp16(bsB + bSt1, Bptr2);
        cp_commit();
    }

    for (int t = 0; t < iters; t++) {
        cp_wait<0>();          // tile t resident (this thread's copies)
        __syncthreads();       // all threads' copies visible; prev compute done

        if (t + 1 < iters) {   // issue tile t+1 into the other buffer
            const int k0 = (t + 1) * 32;
            const uint32_t nb = (uint32_t)((t + 1) & 1);
            cp16(asB + nb * ABUF + aSt0, Aptr + k0);
            cp16(asB + nb * ABUF + aSt1, Aptr2 + k0);
            cp16(bsB + nb * BBUF + bSt0, Bptr + (size_t)k0 * N);
            cp16(bsB + nb * BBUF + bSt1, Bptr2 + (size_t)k0 * N);
            cp_commit();
        }

        const uint32_t buf = (uint32_t)(t & 1);
        const uint32_t aBase = asB + buf * ABUF + aOff;
        const uint32_t bBase = bsB + buf * BBUF + bOff;
#pragma unroll
        for (int ks = 0; ks < 2; ks++) {
            uint32_t af[4][4], bf[4][2];
#pragma unroll
            for (int mt = 0; mt < 4; mt++)
                ldsm_x4(af[mt], aBase + (uint32_t)(mt * 16 * AH + ks * 16) * 2);
#pragma unroll
            for (int nt = 0; nt < 4; nt++)
                ldsm_x2_t(bf[nt], bBase + (uint32_t)(ks * 16 * BH + nt * 8) * 2);
#pragma unroll
            for (int mt = 0; mt < 4; mt++)
#pragma unroll
                for (int nt = 0; nt < 4; nt++)
                    mma_fp16(c[mt][nt], af[mt], bf[nt]);
        }
        __syncthreads();       // done reading buf before it is refilled
    }

    // epilogue: bias add + fp32 store
#pragma unroll
    for (int mt = 0; mt < 4; mt++) {
        const int row = brow + wm + mt * 16 + gid;
#pragma unroll
        for (int nt = 0; nt < 4; nt++) {
            const int col = bcol + wn + nt * 8 + tig * 2;
            const float b0 = bias[col], b1 = bias[col + 1];
            float2 o0 = make_float2(c[mt][nt][0] + b0, c[mt][nt][1] + b1);
            float2 o1 = make_float2(c[mt][nt][2] + b0, c[mt][nt][3] + b1);
            *(float2*)&C[(size_t)row * N + col]       = o0;
            *(float2*)&C[(size_t)(row + 8) * N + col] = o1;
        }
    }
}

// ---------------------------------------------------------------------------
// Split QKV + per-head LayerNorm on Q,K; copy V. Outputs fp16 head-major.
// ---------------------------------------------------------------------------
__global__ __launch_bounds__(256) void qkv_split_ln(
    const float* __restrict__ qkv,
    const float* __restrict__ qg, const float* __restrict__ qb,
    const float* __restrict__ kg, const float* __restrict__ kb,
    __half* __restrict__ qh, __half* __restrict__ kh, __half* __restrict__ vh)
{
    int w = (blockIdx.x * blockDim.x + threadIdx.x) >> 5;
    int lane = threadIdx.x & 31;
    int t = w / LN_ROWS_;      // 0:q 1:k 2:v
    int row = w - t * LN_ROWS_;
    if (t >= 3) return;

    int b = row / (S_ * NH_);
    int rem = row - b * (S_ * NH_);
    int s = rem / NH_;
    int n = rem - s * NH_;

    const float* src = qkv + (size_t)(b * S_ + s) * (3 * H_) + t * H_ + n * HD_;
    __half* dst = (t == 0 ? qh : (t == 1 ? kh : vh)) +
                  ((size_t)(b * NH_ + n) * S_ + s) * HD_;

    float x0 = src[lane];
    float x1 = src[lane + 32];
    if (t == 2) {
        dst[lane]      = __float2half_rn(x0);
        dst[lane + 32] = __float2half_rn(x1);
        return;
    }

    float s1 = x0 + x1;
    float s2 = x0 * x0 + x1 * x1;
#pragma unroll
    for (int o = 16; o > 0; o >>= 1) {
        s1 += __shfl_xor_sync(0xffffffffu, s1, o);
        s2 += __shfl_xor_sync(0xffffffffu, s2, o);
    }
    float mu  = s1 * (1.0f / HD_);
    float var = s2 * (1.0f / HD_) - mu * mu;
    float inv = rsqrtf(var + 1e-5f);

    const float* g  = (t == 0) ? qg : kg;
    const float* be = (t == 0) ? qb : kb;
    dst[lane]      = __float2half_rn((x0 - mu) * inv * g[lane]      + be[lane]);
    dst[lane + 32] = __float2half_rn((x1 - mu) * inv * g[lane + 32] + be[lane + 32]);
}

// ---------------------------------------------------------------------------
// Causal flash attention, fp16 tensor cores. ctx written as fp16.
// ---------------------------------------------------------------------------
#define QST 72
#define KST 72
#define VST 72

__global__ __launch_bounds__(256, 2) void flash_attn_fp16(
    const __half* __restrict__ qh, const __half* __restrict__ kh,
    const __half* __restrict__ vh, __half* __restrict__ ctx)
{
    __shared__ __half Qs[128][QST];
    __shared__ __half Ks[32][KST];
    __shared__ __half Vs[32][VST];

    const int bh  = blockIdx.y;
    const int qt  = blockIdx.x;
    const int tid = threadIdx.x;
    const int lane = tid & 31;
    const int w    = tid >> 5;
    const int gid  = lane >> 2;
    const int tig  = lane & 3;
    const int l8   = lane & 7;
    const int h8   = (lane >> 3) & 1;
    const int h16  = (lane >> 4) & 1;
    const int qbase = qt * 128;
    const int wrow  = w * 16;

    const __half* Q  = qh + (size_t)bh * S_ * HD_ + (size_t)qbase * HD_;
    const __half* Kp = kh + (size_t)bh * S_ * HD_;
    const __half* Vp = vh + (size_t)bh * S_ * HD_;

    for (int i = tid; i < 128 * 8; i += 256) {
        int r = i >> 3, c8 = (i & 7) * 8;
        *(uint4*)&Qs[r][c8] = *(const uint4*)&Q[r * HD_ + c8];
    }
    __syncthreads();

    const uint32_t qsB = (uint32_t)__cvta_generic_to_shared(&Qs[0][0]) +
                         ((uint32_t)(wrow + l8 + h8 * 8) * QST + h16 * 8) * 2;
    uint32_t qa[4][4];
#pragma unroll
    for (int ks = 0; ks < 4; ks++)
        ldsm_x4(qa[ks], qsB + (uint32_t)(ks * 16) * 2);
    __syncthreads();

    const uint32_t ksB = (uint32_t)__cvta_generic_to_shared(&Ks[0][0]) +
                         ((uint32_t)(l8)*KST + h8 * 8) * 2;
    const uint32_t vsB = (uint32_t)__cvta_generic_to_shared(&Vs[0][0]) +
                         ((uint32_t)(l8 + h8 * 8) * VST) * 2;

    float o[8][4];
#pragma unroll
    for (int i = 0; i < 8; i++)
#pragma unroll
        for (int j = 0; j < 4; j++) o[i][j] = 0.f;
    float m0 = -CUDART_INF_F, m1 = -CUDART_INF_F;
    float l0 = 0.f, l1 = 0.f;

    const int r0g = qbase + wrow + gid;
    const int r1g = r0g + 8;
    const int rmaxw = qbase + wrow + 15;
    const int nkt = (qt + 1) * 4;
    const float scl = 0.125f;

    for (int kt = 0; kt < nkt; kt++) {
        const int kbase = kt * 32;
        {
            int r = tid >> 3, c8 = (tid & 7) * 8;
            *(uint4*)&Ks[r][c8] = *(const uint4*)&Kp[(size_t)(kbase + r) * HD_ + c8];
            *(uint4*)&Vs[r][c8] = *(const uint4*)&Vp[(size_t)(kbase + r) * HD_ + c8];
        }
        __syncthreads();

        if (kbase <= rmaxw) {
            float s[4][4];
#pragma unroll
            for (int nt = 0; nt < 4; nt++)
#pragma unroll
                for (int j = 0; j < 4; j++) s[nt][j] = 0.f;
#pragma unroll
            for (int nt = 0; nt < 4; nt++) {
#pragma unroll
                for (int ks = 0; ks < 4; ks++) {
                    uint32_t b[2];
                    ldsm_x2(b, ksB + (uint32_t)(nt * 8 * KST + ks * 16) * 2);
                    mma_fp16(s[nt], qa[ks], b);
                }
            }

            if (kbase + 31 <= qbase + wrow) {
#pragma unroll
                for (int nt = 0; nt < 4; nt++)
#pragma unroll
                    for (int j = 0; j < 4; j++) s[nt][j] *= scl;
            } else {
#pragma unroll
                for (int nt = 0; nt < 4; nt++) {
                    int c0 = kbase + nt * 8 + tig * 2;
                    s[nt][0] = (c0     <= r0g) ? s[nt][0] * scl : -CUDART_INF_F;
                    s[nt][1] = (c0 + 1 <= r0g) ? s[nt][1] * scl : -CUDART_INF_F;
                    s[nt][2] = (c0     <= r1g) ? s[nt][2] * scl : -CUDART_INF_F;
                    s[nt][3] = (c0 + 1 <= r1g) ? s[nt][3] * scl : -CUDART_INF_F;
                }
            }

            float mt0 = fmaxf(fmaxf(s[0][0], s[0][1]), fmaxf(s[1][0], s[1][1]));
            mt0 = fmaxf(mt0, fmaxf(fmaxf(s[2][0], s[2][1]), fmaxf(s[3][0], s[3][1])));
            float mt1 = fmaxf(fmaxf(s[0][2], s[0][3]), fmaxf(s[1][2], s[1][3]));
            mt1 = fmaxf(mt1, fmaxf(fmaxf(s[2][2], s[2][3]), fmaxf(s[3][2], s[3][3])));
            mt0 = fmaxf(mt0, __shfl_xor_sync(0xffffffffu, mt0, 1));
            mt0 = fmaxf(mt0, __shfl_xor_sync(0xffffffffu, mt0, 2));
            mt1 = fmaxf(mt1, __shfl_xor_sync(0xffffffffu, mt1, 1));
            mt1 = fmaxf(mt1, __shfl_xor_sync(0xffffffffu, mt1, 2));

            float mn0 = fmaxf(m0, mt0), mn1 = fmaxf(m1, mt1);
            float a0 = __expf(m0 - mn0), a1 = __expf(m1 - mn1);
            m0 = mn0; m1 = mn1;

            float p[4][4];
            float ps0 = 0.f, ps1 = 0.f;
#pragma unroll
            for (int nt = 0; nt < 4; nt++) {
                p[nt][0] = __expf(s[nt][0] - mn0);
                p[nt][1] = __expf(s[nt][1] - mn0);
                p[nt][2] = __expf(s[nt][2] - mn1);
                p[nt][3] = __expf(s[nt][3] - mn1);
                ps0 += p[nt][0] + p[nt][1];
                ps1 += p[nt][2] + p[nt][3];
            }
            ps0 += __shfl_xor_sync(0xffffffffu, ps0, 1);
            ps0 += __shfl_xor_sync(0xffffffffu, ps0, 2);
            ps1 += __shfl_xor_sync(0xffffffffu, ps1, 1);
            ps1 += __shfl_xor_sync(0xffffffffu, ps1, 2);
            l0 = l0 * a0 + ps0;
            l1 = l1 * a1 + ps1;

            uint32_t pa[2][4];
#pragma unroll
            for (int ks = 0; ks < 2; ks++) {
                pa[ks][0] = h2r(p[2 * ks][0],     p[2 * ks][1]);
                pa[ks][1] = h2r(p[2 * ks][2],     p[2 * ks][3]);
                pa[ks][2] = h2r(p[2 * ks + 1][0], p[2 * ks + 1][1]);
                pa[ks][3] = h2r(p[2 * ks + 1][2], p[2 * ks + 1][3]);
            }

#pragma unroll
            for (int nt = 0; nt < 8; nt++) {
                o[nt][0] *= a0; o[nt][1] *= a0;
                o[nt][2] *= a1; o[nt][3] *= a1;
            }
#pragma unroll
            for (int nt = 0; nt < 8; nt++) {
#pragma unroll
                for (int ks = 0; ks < 2; ks++) {
                    uint32_t b[2];
                    ldsm_x2_t(b, vsB + (uint32_t)(ks * 16 * VST + nt * 8) * 2);
                    mma_fp16(o[nt], pa[ks], b);
                }
            }
        }
        __syncthreads();
    }

    // normalize + write ctx [B,S,H] fp16
    const int bb = bh >> 4;
    const int nh = bh & 15;
    const float inv0 = 1.0f / l0;
    const float inv1 = 1.0f / l1;
    __half* orow0 = ctx + (size_t)(bb * S_ + r0g) * H_ + nh * HD_;
    __half* orow1 = ctx + (size_t)(bb * S_ + r1g) * H_ + nh * HD_;
#pragma unroll
    for (int nt = 0; nt < 8; nt++) {
        int col = nt * 8 + tig * 2;
        *(__half2*)&orow0[col] = __floats2half2_rn(o[nt][0] * inv0, o[nt][1] * inv0);
        *(__half2*)&orow1[col] = __floats2half2_rn(o[nt][2] * inv1, o[nt][3] * inv1);
    }
}

// ---------------------------------------------------------------------------
extern "C" void kernel_launch(void* const* d_in, const int* in_sizes, int n_in,
                              void* d_out, int out_size)
{
    const float* hs = (const float*)d_in[0];
    const float* Wa = (const float*)d_in[1];
    const float* ba = (const float*)d_in[2];
    const float* Wp = (const float*)d_in[3];
    const float* bp = (const float*)d_in[4];
    const float* qg = (const float*)d_in[5];
    const float* qb = (const float*)d_in[6];
    const float* kg = (const float*)d_in[7];
    const float* kb = (const float*)d_in[8];
    float* out = (float*)d_out;

    float *qkv;
    __half *hsh, *wah, *wph, *qh, *kh, *vh, *ctxh;
    cudaGetSymbolAddress((void**)&qkv, g_qkv);
    cudaGetSymbolAddress((void**)&hsh, g_hsh);
    cudaGetSymbolAddress((void**)&wah, g_wah);
    cudaGetSymbolAddress((void**)&wph, g_wph);
    cudaGetSymbolAddress((void**)&qh,  g_qh);
    cudaGetSymbolAddress((void**)&kh,  g_kh);
    cudaGetSymbolAddress((void**)&vh,  g_vh);
    cudaGetSymbolAddress((void**)&ctxh, g_ctxh);

    // 0) fp32 -> fp16 input conversions
    {
        int n4;
        n4 = (MROWS_ * H_) / 4;
        f2h<<<(n4 + 255) / 256, 256>>>((const float4*)hs, (uint2*)hsh, n4);
        n4 = (H_ * 3 * H_) / 4;
        f2h<<<(n4 + 255) / 256, 256>>>((const float4*)Wa, (uint2*)wah, n4);
        n4 = (H_ * H_) / 4;
        f2h<<<(n4 + 255) / 256, 256>>>((const float4*)Wp, (uint2*)wph, n4);
    }

    // 1) QKV GEMM: [4096,1024] @ [1024,3072] + bias (fp16 cp.async pipeline)
    gemm_fp16a<<<dim3(3 * H_ / 128, MROWS_ / 128), 256>>>(hsh, wah, ba, qkv,
                                                          MROWS_, 3 * H_, H_);

    // 2) split + QK layernorm + V copy (fp16 outputs)
    {
        int warps = 3 * LN_ROWS_;
        int blocks = (warps * 32 + 255) / 256;
        qkv_split_ln<<<blocks, 256>>>(qkv, qg, qb, kg, kb, qh, kh, vh);
    }

    // 3) causal flash attention (fp16; ctx written fp16)
    flash_attn_fp16<<<dim3(S_ / 128, B_ * NH_), 256>>>(qh, kh, vh, ctxh);

    // 4) output projection: [4096,1024] @ [1024,1024] + bias
    gemm_fp16a<<<dim3(H_ / 128, MROWS_ / 128), 256>>>(ctxh, wph, bp, out,
                                                      MROWS_, H_, H_);
}

// round 10
// speedup vs baseline: 2.2220x; 1.0147x over previous
#include <cuda_runtime.h>
#include <cuda_fp16.h>
#include <math_constants.h>
#include <cstdint>

// Problem constants
#define B_  2
#define S_  2048
#define H_  1024
#define NH_ 16
#define HD_ 64
#define MROWS_ (B_ * S_)          // 4096
#define LN_ROWS_ (B_ * S_ * NH_)  // 65536

// Scratch (device globals — allocation-free rule)
__device__ __half g_qkvh[(size_t)MROWS_ * 3 * H_];  // [4096, 3072] fp16
__device__ __half g_hsh[(size_t)MROWS_ * H_];       // hs in fp16
__device__ __half g_wah[(size_t)H_ * 3 * H_];       // W_attn fp16
__device__ __half g_wph[(size_t)H_ * H_];           // W_proj fp16
__device__ __half g_qh [(size_t)MROWS_ * H_];       // [B*NH, S, HD] fp16
__device__ __half g_kh [(size_t)MROWS_ * H_];
__device__ __half g_vh [(size_t)MROWS_ * H_];
__device__ __half g_ctxh[(size_t)MROWS_ * H_];      // [B, S, H] fp16

// ---------------------------------------------------------------------------
// helpers
// ---------------------------------------------------------------------------
__device__ __forceinline__ uint32_t h2r(float lo, float hi) {
    __half2 h = __floats2half2_rn(lo, hi);
    return *reinterpret_cast<uint32_t*>(&h);
}

__device__ __forceinline__ void mma_fp16(float c[4], const uint32_t a[4],
                                         const uint32_t b[2]) {
    asm volatile(
        "mma.sync.aligned.m16n8k16.row.col.f32.f16.f16.f32 "
        "{%0,%1,%2,%3}, {%4,%5,%6,%7}, {%8,%9}, {%0,%1,%2,%3};"
        : "+f"(c[0]), "+f"(c[1]), "+f"(c[2]), "+f"(c[3])
        : "r"(a[0]), "r"(a[1]), "r"(a[2]), "r"(a[3]), "r"(b[0]), "r"(b[1]));
}

__device__ __forceinline__ void ldsm_x4(uint32_t r[4], uint32_t addr) {
    asm volatile("ldmatrix.sync.aligned.m8n8.x4.shared.b16 {%0,%1,%2,%3}, [%4];"
                 : "=r"(r[0]), "=r"(r[1]), "=r"(r[2]), "=r"(r[3]) : "r"(addr));
}

__device__ __forceinline__ void ldsm_x2(uint32_t r[2], uint32_t addr) {
    asm volatile("ldmatrix.sync.aligned.m8n8.x2.shared.b16 {%0,%1}, [%2];"
                 : "=r"(r[0]), "=r"(r[1]) : "r"(addr));
}

__device__ __forceinline__ void ldsm_x2_t(uint32_t r[2], uint32_t addr) {
    asm volatile("ldmatrix.sync.aligned.m8n8.x2.trans.shared.b16 {%0,%1}, [%2];"
                 : "=r"(r[0]), "=r"(r[1]) : "r"(addr));
}

__device__ __forceinline__ void cp16(uint32_t smem, const void* gmem) {
    asm volatile("cp.async.cg.shared.global [%0], [%1], 16;" ::
                 "r"(smem), "l"(gmem));
}
__device__ __forceinline__ void cp_commit() {
    asm volatile("cp.async.commit_group;");
}
template <int N>
__device__ __forceinline__ void cp_wait() {
    asm volatile("cp.async.wait_group %0;" :: "n"(N));
}

// ---------------------------------------------------------------------------
// fp32 -> fp16 conversion (vectorized, n % 4 == 0)
// ---------------------------------------------------------------------------
__global__ __launch_bounds__(256) void f2h(const float4* __restrict__ in,
                                           uint2* __restrict__ out, int n4)
{
    int i = blockIdx.x * blockDim.x + threadIdx.x;
    if (i < n4) {
        float4 v = in[i];
        uint2 o;
        o.x = h2r(v.x, v.y);
        o.y = h2r(v.z, v.w);
        out[i] = o;
    }
}

// ---------------------------------------------------------------------------
// FP16 tensor-core GEMM, 4-stage cp.async pipeline, BK=16.
// C[M,N] = A[M,K] @ B[K,N] + bias[N].  A,B fp16; C fp32 or fp16 (template).
// FIX vs R8: cp_commit() every iteration (empty groups in the tail), so
// cp_wait<STAGES-2> always guarantees tile t is resident — the R8 tail
// under-synchronization read tiles 62/63 while still in flight.
// ---------------------------------------------------------------------------
#define AH 24
#define BH 136
#define STAGES 4

template <typename OutT>
__global__ __launch_bounds__(256, 2) void gemm_fp16p(
    const __half* __restrict__ A, const __half* __restrict__ Bm,
    const float* __restrict__ bias, OutT* __restrict__ C,
    int M, int N, int K)
{
    __shared__ __half As[STAGES][128][AH];
    __shared__ __half Bs[STAGES][16][BH];

    const int tid  = threadIdx.x;
    const int lane = tid & 31;
    const int warp = tid >> 5;
    const int wm = (warp & 1) * 64;
    const int wn = (warp >> 1) * 32;
    const int gid = lane >> 2;
    const int tig = lane & 3;
    const int brow = blockIdx.y * 128;
    const int bcol = blockIdx.x * 128;

    // A tile 128x16 halfs (4KB): row = tid>>1, col halfs = (tid&1)*8
    const int aRow = tid >> 1;
    const int aCol = (tid & 1) * 8;
    const __half* Aptr = A + (size_t)(brow + aRow) * K + aCol;

    // B tile 16x128 halfs (4KB): row = tid>>4, col halfs = (tid&15)*8
    const int bRow = tid >> 4;
    const int bCol = (tid & 15) * 8;
    const __half* Bptr = Bm + (size_t)bRow * N + bcol + bCol;

    const uint32_t asB = (uint32_t)__cvta_generic_to_shared(&As[0][0][0]);
    const uint32_t bsB = (uint32_t)__cvta_generic_to_shared(&Bs[0][0][0]);
    const uint32_t ABUF = 128 * AH * 2;
    const uint32_t BBUF = 16 * BH * 2;
    const uint32_t aSt = (uint32_t)(aRow * AH + aCol) * 2;
    const uint32_t bSt = (uint32_t)(bRow * BH + bCol) * 2;

    float c[4][4][4];
#pragma unroll
    for (int i = 0; i < 4; i++)
#pragma unroll
        for (int j = 0; j < 4; j++)
#pragma unroll
            for (int r = 0; r < 4; r++) c[i][j][r] = 0.f;

    // ldsm per-thread coords
    const int l8  = lane & 7;
    const int h8  = (lane >> 3) & 1;
    const int h16 = (lane >> 4) & 1;
    const uint32_t aOff = ((uint32_t)(wm + l8 + h8 * 8) * AH + h16 * 8) * 2;
    const uint32_t bOff = ((uint32_t)(l8 + h8 * 8) * BH + wn) * 2;

    const int iters = K / 16;   // 64

    // prologue: issue tiles 0..STAGES-2
#pragma unroll
    for (int s = 0; s < STAGES - 1; s++) {
        cp16(asB + (uint32_t)s * ABUF + aSt, Aptr + s * 16);
        cp16(bsB + (uint32_t)s * BBUF + bSt, Bptr + (size_t)(s * 16) * N);
        cp_commit();
    }

    for (int t = 0; t < iters; t++) {
        cp_wait<STAGES - 2>();   // group t retired -> tile t resident
        __syncthreads();         // visible to all; prev compute done

        if (t + STAGES - 1 < iters) {
            const int k0 = (t + STAGES - 1) * 16;
            const uint32_t st = (uint32_t)((t + STAGES - 1) & (STAGES - 1));
            cp16(asB + st * ABUF + aSt, Aptr + k0);
            cp16(bsB + st * BBUF + bSt, Bptr + (size_t)k0 * N);
        }
        cp_commit();             // ALWAYS commit (empty group in tail) — keeps
                                 // group index aligned with tile index

        const uint32_t buf = (uint32_t)(t & (STAGES - 1));
        const uint32_t aBase = asB + buf * ABUF + aOff;
        const uint32_t bBase = bsB + buf * BBUF + bOff;
        uint32_t af[4][4], bf[4][2];
#pragma unroll
        for (int mt = 0; mt < 4; mt++)
            ldsm_x4(af[mt], aBase + (uint32_t)(mt * 16 * AH) * 2);
#pragma unroll
        for (int nt = 0; nt < 4; nt++)
            ldsm_x2_t(bf[nt], bBase + (uint32_t)(nt * 8) * 2);
#pragma unroll
        for (int mt = 0; mt < 4; mt++)
#pragma unroll
            for (int nt = 0; nt < 4; nt++)
                mma_fp16(c[mt][nt], af[mt], bf[nt]);
    }

    // epilogue: bias add + store (fp32 or fp16)
#pragma unroll
    for (int mt = 0; mt < 4; mt++) {
        const int row = brow + wm + mt * 16 + gid;
#pragma unroll
        for (int nt = 0; nt < 4; nt++) {
            const int col = bcol + wn + nt * 8 + tig * 2;
            const float b0 = bias[col], b1 = bias[col + 1];
            float v00 = c[mt][nt][0] + b0, v01 = c[mt][nt][1] + b1;
            float v10 = c[mt][nt][2] + b0, v11 = c[mt][nt][3] + b1;
            if (sizeof(OutT) == 4) {
                *(float2*)&((float*)C)[(size_t)row * N + col] = make_float2(v00, v01);
                *(float2*)&((float*)C)[(size_t)(row + 8) * N + col] = make_float2(v10, v11);
            } else {
                *(__half2*)&((__half*)C)[(size_t)row * N + col] = __floats2half2_rn(v00, v01);
                *(__half2*)&((__half*)C)[(size_t)(row + 8) * N + col] = __floats2half2_rn(v10, v11);
            }
        }
    }
}

// ---------------------------------------------------------------------------
// Split QKV (fp16) + per-head LayerNorm on Q,K; copy V. fp16 head-major out.
// ---------------------------------------------------------------------------
__global__ __launch_bounds__(256) void qkv_split_ln(
    const __half* __restrict__ qkv,
    const float* __restrict__ qg, const float* __restrict__ qb,
    const float* __restrict__ kg, const float* __restrict__ kb,
    __half* __restrict__ qh, __half* __restrict__ kh, __half* __restrict__ vh)
{
    int w = (blockIdx.x * blockDim.x + threadIdx.x) >> 5;
    int lane = threadIdx.x & 31;
    int t = w / LN_ROWS_;      // 0:q 1:k 2:v
    int row = w - t * LN_ROWS_;
    if (t >= 3) return;

    int b = row / (S_ * NH_);
    int rem = row - b * (S_ * NH_);
    int s = rem / NH_;
    int n = rem - s * NH_;

    const __half* src = qkv + (size_t)(b * S_ + s) * (3 * H_) + t * H_ + n * HD_;
    __half* dst = (t == 0 ? qh : (t == 1 ? kh : vh)) +
                  ((size_t)(b * NH_ + n) * S_ + s) * HD_;

    __half2 xv = *(const __half2*)&src[lane * 2];
    float x0 = __half2float(xv.x);
    float x1 = __half2float(xv.y);
    if (t == 2) {
        *(__half2*)&dst[lane * 2] = xv;
        return;
    }

    float s1 = x0 + x1;
    float s2 = x0 * x0 + x1 * x1;
#pragma unroll
    for (int o = 16; o > 0; o >>= 1) {
        s1 += __shfl_xor_sync(0xffffffffu, s1, o);
        s2 += __shfl_xor_sync(0xffffffffu, s2, o);
    }
    float mu  = s1 * (1.0f / HD_);
    float var = s2 * (1.0f / HD_) - mu * mu;
    float inv = rsqrtf(var + 1e-5f);

    const float* g  = (t == 0) ? qg : kg;
    const float* be = (t == 0) ? qb : kb;
    float y0 = (x0 - mu) * inv * g[lane * 2]     + be[lane * 2];
    float y1 = (x1 - mu) * inv * g[lane * 2 + 1] + be[lane * 2 + 1];
    *(__half2*)&dst[lane * 2] = __floats2half2_rn(y0, y1);
}

// ---------------------------------------------------------------------------
// Causal flash attention, fp16 tensor cores. ctx written as fp16.
// ---------------------------------------------------------------------------
#define QST 72
#define KST 72
#define VST 72

__global__ __launch_bounds__(256, 2) void flash_attn_fp16(
    const __half* __restrict__ qh, const __half* __restrict__ kh,
    const __half* __restrict__ vh, __half* __restrict__ ctx)
{
    __shared__ __half Qs[128][QST];
    __shared__ __half Ks[32][KST];
    __shared__ __half Vs[32][VST];

    const int bh  = blockIdx.y;
    const int qt  = blockIdx.x;
    const int tid = threadIdx.x;
    const int lane = tid & 31;
    const int w    = tid >> 5;
    const int gid  = lane >> 2;
    const int tig  = lane & 3;
    const int l8   = lane & 7;
    const int h8   = (lane >> 3) & 1;
    const int h16  = (lane >> 4) & 1;
    const int qbase = qt * 128;
    const int wrow  = w * 16;

    const __half* Q  = qh + (size_t)bh * S_ * HD_ + (size_t)qbase * HD_;
    const __half* Kp = kh + (size_t)bh * S_ * HD_;
    const __half* Vp = vh + (size_t)bh * S_ * HD_;

    for (int i = tid; i < 128 * 8; i += 256) {
        int r = i >> 3, c8 = (i & 7) * 8;
        *(uint4*)&Qs[r][c8] = *(const uint4*)&Q[r * HD_ + c8];
    }
    __syncthreads();

    const uint32_t qsB = (uint32_t)__cvta_generic_to_shared(&Qs[0][0]) +
                         ((uint32_t)(wrow + l8 + h8 * 8) * QST + h16 * 8) * 2;
    uint32_t qa[4][4];
#pragma unroll
    for (int ks = 0; ks < 4; ks++)
        ldsm_x4(qa[ks], qsB + (uint32_t)(ks * 16) * 2);
    __syncthreads();

    const uint32_t ksB = (uint32_t)__cvta_generic_to_shared(&Ks[0][0]) +
                         ((uint32_t)(l8)*KST + h8 * 8) * 2;
    const uint32_t vsB = (uint32_t)__cvta_generic_to_shared(&Vs[0][0]) +
                         ((uint32_t)(l8 + h8 * 8) * VST) * 2;

    float o[8][4];
#pragma unroll
    for (int i = 0; i < 8; i++)
#pragma unroll
        for (int j = 0; j < 4; j++) o[i][j] = 0.f;
    float m0 = -CUDART_INF_F, m1 = -CUDART_INF_F;
    float l0 = 0.f, l1 = 0.f;

    const int r0g = qbase + wrow + gid;
    const int r1g = r0g + 8;
    const int rmaxw = qbase + wrow + 15;
    const int nkt = (qt + 1) * 4;
    const float scl = 0.125f;

    for (int kt = 0; kt < nkt; kt++) {
        const int kbase = kt * 32;
        {
            int r = tid >> 3, c8 = (tid & 7) * 8;
            *(uint4*)&Ks[r][c8] = *(const uint4*)&Kp[(size_t)(kbase + r) * HD_ + c8];
            *(uint4*)&Vs[r][c8] = *(const uint4*)&Vp[(size_t)(kbase + r) * HD_ + c8];
        }
        __syncthreads();

        if (kbase <= rmaxw) {
            float s[4][4];
#pragma unroll
            for (int nt = 0; nt < 4; nt++)
#pragma unroll
                for (int j = 0; j < 4; j++) s[nt][j] = 0.f;
#pragma unroll
            for (int nt = 0; nt < 4; nt++) {
#pragma unroll
                for (int ks = 0; ks < 4; ks++) {
                    uint32_t b[2];
                    ldsm_x2(b, ksB + (uint32_t)(nt * 8 * KST + ks * 16) * 2);
                    mma_fp16(s[nt], qa[ks], b);
                }
            }

            if (kbase + 31 <= qbase + wrow) {
#pragma unroll
                for (int nt = 0; nt < 4; nt++)
#pragma unroll
                    for (int j = 0; j < 4; j++) s[nt][j] *= scl;
            } else {
#pragma unroll
                for (int nt = 0; nt < 4; nt++) {
                    int c0 = kbase + nt * 8 + tig * 2;
                    s[nt][0] = (c0     <= r0g) ? s[nt][0] * scl : -CUDART_INF_F;
                    s[nt][1] = (c0 + 1 <= r0g) ? s[nt][1] * scl : -CUDART_INF_F;
                    s[nt][2] = (c0     <= r1g) ? s[nt][2] * scl : -CUDART_INF_F;
                    s[nt][3] = (c0 + 1 <= r1g) ? s[nt][3] * scl : -CUDART_INF_F;
                }
            }

            float mt0 = fmaxf(fmaxf(s[0][0], s[0][1]), fmaxf(s[1][0], s[1][1]));
            mt0 = fmaxf(mt0, fmaxf(fmaxf(s[2][0], s[2][1]), fmaxf(s[3][0], s[3][1])));
            float mt1 = fmaxf(fmaxf(s[0][2], s[0][3]), fmaxf(s[1][2], s[1][3]));
            mt1 = fmaxf(mt1, fmaxf(fmaxf(s[2][2], s[2][3]), fmaxf(s[3][2], s[3][3])));
            mt0 = fmaxf(mt0, __shfl_xor_sync(0xffffffffu, mt0, 1));
            mt0 = fmaxf(mt0, __shfl_xor_sync(0xffffffffu, mt0, 2));
            mt1 = fmaxf(mt1, __shfl_xor_sync(0xffffffffu, mt1, 1));
            mt1 = fmaxf(mt1, __shfl_xor_sync(0xffffffffu, mt1, 2));

            float mn0 = fmaxf(m0, mt0), mn1 = fmaxf(m1, mt1);
            float a0 = __expf(m0 - mn0), a1 = __expf(m1 - mn1);
            m0 = mn0; m1 = mn1;

            float p[4][4];
            float ps0 = 0.f, ps1 = 0.f;
#pragma unroll
            for (int nt = 0; nt < 4; nt++) {
                p[nt][0] = __expf(s[nt][0] - mn0);
                p[nt][1] = __expf(s[nt][1] - mn0);
                p[nt][2] = __expf(s[nt][2] - mn1);
                p[nt][3] = __expf(s[nt][3] - mn1);
                ps0 += p[nt][0] + p[nt][1];
                ps1 += p[nt][2] + p[nt][3];
            }
            ps0 += __shfl_xor_sync(0xffffffffu, ps0, 1);
            ps0 += __shfl_xor_sync(0xffffffffu, ps0, 2);
            ps1 += __shfl_xor_sync(0xffffffffu, ps1, 1);
            ps1 += __shfl_xor_sync(0xffffffffu, ps1, 2);
            l0 = l0 * a0 + ps0;
            l1 = l1 * a1 + ps1;

            uint32_t pa[2][4];
#pragma unroll
            for (int ks = 0; ks < 2; ks++) {
                pa[ks][0] = h2r(p[2 * ks][0],     p[2 * ks][1]);
                pa[ks][1] = h2r(p[2 * ks][2],     p[2 * ks][3]);
                pa[ks][2] = h2r(p[2 * ks + 1][0], p[2 * ks + 1][1]);
                pa[ks][3] = h2r(p[2 * ks + 1][2], p[2 * ks + 1][3]);
            }

#pragma unroll
            for (int nt = 0; nt < 8; nt++) {
                o[nt][0] *= a0; o[nt][1] *= a0;
                o[nt][2] *= a1; o[nt][3] *= a1;
            }
#pragma unroll
            for (int nt = 0; nt < 8; nt++) {
#pragma unroll
                for (int ks = 0; ks < 2; ks++) {
                    uint32_t b[2];
                    ldsm_x2_t(b, vsB + (uint32_t)(ks * 16 * VST + nt * 8) * 2);
                    mma_fp16(o[nt], pa[ks], b);
                }
            }
        }
        __syncthreads();
    }

    const int bb = bh >> 4;
    const int nh = bh & 15;
    const float inv0 = 1.0f / l0;
    const float inv1 = 1.0f / l1;
    __half* orow0 = ctx + (size_t)(bb * S_ + r0g) * H_ + nh * HD_;
    __half* orow1 = ctx + (size_t)(bb * S_ + r1g) * H_ + nh * HD_;
#pragma unroll
    for (int nt = 0; nt < 8; nt++) {
        int col = nt * 8 + tig * 2;
        *(__half2*)&orow0[col] = __floats2half2_rn(o[nt][0] * inv0, o[nt][1] * inv0);
        *(__half2*)&orow1[col] = __floats2half2_rn(o[nt][2] * inv1, o[nt][3] * inv1);
    }
}

// ---------------------------------------------------------------------------
extern "C" void kernel_launch(void* const* d_in, const int* in_sizes, int n_in,
                              void* d_out, int out_size)
{
    const float* hs = (const float*)d_in[0];
    const float* Wa = (const float*)d_in[1];
    const float* ba = (const float*)d_in[2];
    const float* Wp = (const float*)d_in[3];
    const float* bp = (const float*)d_in[4];
    const float* qg = (const float*)d_in[5];
    const float* qb = (const float*)d_in[6];
    const float* kg = (const float*)d_in[7];
    const float* kb = (const float*)d_in[8];
    float* out = (float*)d_out;

    __half *qkvh, *hsh, *wah, *wph, *qh, *kh, *vh, *ctxh;
    cudaGetSymbolAddress((void**)&qkvh, g_qkvh);
    cudaGetSymbolAddress((void**)&hsh, g_hsh);
    cudaGetSymbolAddress((void**)&wah, g_wah);
    cudaGetSymbolAddress((void**)&wph, g_wph);
    cudaGetSymbolAddress((void**)&qh,  g_qh);
    cudaGetSymbolAddress((void**)&kh,  g_kh);
    cudaGetSymbolAddress((void**)&vh,  g_vh);
    cudaGetSymbolAddress((void**)&ctxh, g_ctxh);

    // 0) fp32 -> fp16 input conversions
    {
        int n4;
        n4 = (MROWS_ * H_) / 4;
        f2h<<<(n4 + 255) / 256, 256>>>((const float4*)hs, (uint2*)hsh, n4);
        n4 = (H_ * 3 * H_) / 4;
        f2h<<<(n4 + 255) / 256, 256>>>((const float4*)Wa, (uint2*)wah, n4);
        n4 = (H_ * H_) / 4;
        f2h<<<(n4 + 255) / 256, 256>>>((const float4*)Wp, (uint2*)wph, n4);
    }

    // 1) QKV GEMM (fp16 out): [4096,1024] @ [1024,3072] + bias
    gemm_fp16p<__half><<<dim3(3 * H_ / 128, MROWS_ / 128), 256>>>(
        hsh, wah, ba, qkvh, MROWS_, 3 * H_, H_);

    // 2) split + QK layernorm + V copy (fp16 in/out)
    {
        int warps = 3 * LN_ROWS_;
        int blocks = (warps * 32 + 255) / 256;
        qkv_split_ln<<<blocks, 256>>>(qkvh, qg, qb, kg, kb, qh, kh, vh);
    }

    // 3) causal flash attention (fp16; ctx fp16)
    flash_attn_fp16<<<dim3(S_ / 128, B_ * NH_), 256>>>(qh, kh, vh, ctxh);

    // 4) output projection (fp32 out): [4096,1024] @ [1024,1024] + bias
    gemm_fp16p<float><<<dim3(H_ / 128, MROWS_ / 128), 256>>>(
        ctxh, wph, bp, out, MROWS_, H_, H_);
}

// round 11
// speedup vs baseline: 2.3828x; 1.0723x over previous
#include <cuda_runtime.h>
#include <cuda_fp16.h>
#include <math_constants.h>
#include <cstdint>

// Problem constants
#define B_  2
#define S_  2048
#define H_  1024
#define NH_ 16
#define HD_ 64
#define MROWS_ (B_ * S_)          // 4096
#define LN_ROWS_ (B_ * S_ * NH_)  // 65536

// Scratch (device globals — allocation-free rule)
__device__ __half g_qkvh[(size_t)MROWS_ * 3 * H_];  // [4096, 3072] fp16
__device__ __half g_hsh[(size_t)MROWS_ * H_];       // hs in fp16
__device__ __half g_wah[(size_t)H_ * 3 * H_];       // W_attn fp16
__device__ __half g_wph[(size_t)H_ * H_];           // W_proj fp16
__device__ __half g_qh [(size_t)MROWS_ * H_];       // [B*NH, S, HD] fp16
__device__ __half g_kh [(size_t)MROWS_ * H_];
__device__ __half g_vh [(size_t)MROWS_ * H_];
__device__ __half g_ctxh[(size_t)MROWS_ * H_];      // [B, S, H] fp16

// ---------------------------------------------------------------------------
// helpers
// ---------------------------------------------------------------------------
__device__ __forceinline__ uint32_t h2r(float lo, float hi) {
    __half2 h = __floats2half2_rn(lo, hi);
    return *reinterpret_cast<uint32_t*>(&h);
}

__device__ __forceinline__ void mma_fp16(float c[4], const uint32_t a[4],
                                         const uint32_t b[2]) {
    asm volatile(
        "mma.sync.aligned.m16n8k16.row.col.f32.f16.f16.f32 "
        "{%0,%1,%2,%3}, {%4,%5,%6,%7}, {%8,%9}, {%0,%1,%2,%3};"
        : "+f"(c[0]), "+f"(c[1]), "+f"(c[2]), "+f"(c[3])
        : "r"(a[0]), "r"(a[1]), "r"(a[2]), "r"(a[3]), "r"(b[0]), "r"(b[1]));
}

__device__ __forceinline__ void ldsm_x4(uint32_t r[4], uint32_t addr) {
    asm volatile("ldmatrix.sync.aligned.m8n8.x4.shared.b16 {%0,%1,%2,%3}, [%4];"
                 : "=r"(r[0]), "=r"(r[1]), "=r"(r[2]), "=r"(r[3]) : "r"(addr));
}

__device__ __forceinline__ void ldsm_x4_t(uint32_t r[4], uint32_t addr) {
    asm volatile("ldmatrix.sync.aligned.m8n8.x4.trans.shared.b16 {%0,%1,%2,%3}, [%4];"
                 : "=r"(r[0]), "=r"(r[1]), "=r"(r[2]), "=r"(r[3]) : "r"(addr));
}

__device__ __forceinline__ void cp16(uint32_t smem, const void* gmem) {
    asm volatile("cp.async.cg.shared.global [%0], [%1], 16;" ::
                 "r"(smem), "l"(gmem));
}
__device__ __forceinline__ void cp_commit() {
    asm volatile("cp.async.commit_group;");
}
template <int N>
__device__ __forceinline__ void cp_wait() {
    asm volatile("cp.async.wait_group %0;" :: "n"(N));
}

// ---------------------------------------------------------------------------
// fp32 -> fp16 conversion (vectorized, n % 4 == 0)
// ---------------------------------------------------------------------------
__global__ __launch_bounds__(256) void f2h(const float4* __restrict__ in,
                                           uint2* __restrict__ out, int n4)
{
    int i = blockIdx.x * blockDim.x + threadIdx.x;
    if (i < n4) {
        float4 v = in[i];
        uint2 o;
        o.x = h2r(v.x, v.y);
        o.y = h2r(v.z, v.w);
        out[i] = o;
    }
}

// ---------------------------------------------------------------------------
// FP16 tensor-core GEMM, 4-stage cp.async pipeline, BK=16.
// C[M,N] = A[M,K] @ B[K,N] + bias[N].  A,B fp16; C fp32 or fp16 (template).
// B fragments now via ldmatrix.x4.trans (2 LDSM/iter instead of 4).
// ---------------------------------------------------------------------------
#define AH 24
#define BH 136
#define STAGES 4

template <typename OutT>
__global__ __launch_bounds__(256, 2) void gemm_fp16p(
    const __half* __restrict__ A, const __half* __restrict__ Bm,
    const float* __restrict__ bias, OutT* __restrict__ C,
    int M, int N, int K)
{
    __shared__ __half As[STAGES][128][AH];
    __shared__ __half Bs[STAGES][16][BH];

    const int tid  = threadIdx.x;
    const int lane = tid & 31;
    const int warp = tid >> 5;
    const int wm = (warp & 1) * 64;
    const int wn = (warp >> 1) * 32;
    const int gid = lane >> 2;
    const int tig = lane & 3;
    const int brow = blockIdx.y * 128;
    const int bcol = blockIdx.x * 128;

    // A tile 128x16 halfs (4KB): row = tid>>1, col halfs = (tid&1)*8
    const int aRow = tid >> 1;
    const int aCol = (tid & 1) * 8;
    const __half* Aptr = A + (size_t)(brow + aRow) * K + aCol;

    // B tile 16x128 halfs (4KB): row = tid>>4, col halfs = (tid&15)*8
    const int bRow = tid >> 4;
    const int bCol = (tid & 15) * 8;
    const __half* Bptr = Bm + (size_t)bRow * N + bcol + bCol;

    const uint32_t asB = (uint32_t)__cvta_generic_to_shared(&As[0][0][0]);
    const uint32_t bsB = (uint32_t)__cvta_generic_to_shared(&Bs[0][0][0]);
    const uint32_t ABUF = 128 * AH * 2;
    const uint32_t BBUF = 16 * BH * 2;
    const uint32_t aSt = (uint32_t)(aRow * AH + aCol) * 2;
    const uint32_t bSt = (uint32_t)(bRow * BH + bCol) * 2;

    float c[4][4][4];
#pragma unroll
    for (int i = 0; i < 4; i++)
#pragma unroll
        for (int j = 0; j < 4; j++)
#pragma unroll
            for (int r = 0; r < 4; r++) c[i][j][r] = 0.f;

    // ldsm per-thread coords
    const int l8  = lane & 7;
    const int h8  = (lane >> 3) & 1;
    const int h16 = (lane >> 4) & 1;
    const uint32_t aOff = ((uint32_t)(wm + l8 + h8 * 8) * AH + h16 * 8) * 2;
    // B x4-trans: lanes 0-15 -> rows k=l8+h8*8 at col wn (matrices 0,1 = nt even);
    //             lanes 16-31 -> same rows at col wn+8 (matrices 2,3 = nt odd)
    const uint32_t bOff = ((uint32_t)(l8 + h8 * 8) * BH + wn + h16 * 8) * 2;

    const int iters = K / 16;   // 64

    // prologue: issue tiles 0..STAGES-2
#pragma unroll
    for (int s = 0; s < STAGES - 1; s++) {
        cp16(asB + (uint32_t)s * ABUF + aSt, Aptr + s * 16);
        cp16(bsB + (uint32_t)s * BBUF + bSt, Bptr + (size_t)(s * 16) * N);
        cp_commit();
    }

    for (int t = 0; t < iters; t++) {
        cp_wait<STAGES - 2>();   // group t retired -> tile t resident
        __syncthreads();         // visible to all; prev compute done

        if (t + STAGES - 1 < iters) {
            const int k0 = (t + STAGES - 1) * 16;
            const uint32_t st = (uint32_t)((t + STAGES - 1) & (STAGES - 1));
            cp16(asB + st * ABUF + aSt, Aptr + k0);
            cp16(bsB + st * BBUF + bSt, Bptr + (size_t)k0 * N);
        }
        cp_commit();             // ALWAYS commit (empty group in tail)

        const uint32_t buf = (uint32_t)(t & (STAGES - 1));
        const uint32_t aBase = asB + buf * ABUF + aOff;
        const uint32_t bBase = bsB + buf * BBUF + bOff;
        uint32_t af[4][4], bfr[2][4];
#pragma unroll
        for (int mt = 0; mt < 4; mt++)
            ldsm_x4(af[mt], aBase + (uint32_t)(mt * 16 * AH) * 2);
#pragma unroll
        for (int np = 0; np < 2; np++)
            ldsm_x4_t(bfr[np], bBase + (uint32_t)(np * 16) * 2);
#pragma unroll
        for (int mt = 0; mt < 4; mt++)
#pragma unroll
            for (int np = 0; np < 2; np++) {
                mma_fp16(c[mt][2 * np],     af[mt], &bfr[np][0]);
                mma_fp16(c[mt][2 * np + 1], af[mt], &bfr[np][2]);
            }
    }

    // epilogue: bias add + store (fp32 or fp16)
#pragma unroll
    for (int mt = 0; mt < 4; mt++) {
        const int row = brow + wm + mt * 16 + gid;
#pragma unroll
        for (int nt = 0; nt < 4; nt++) {
            const int col = bcol + wn + nt * 8 + tig * 2;
            const float b0 = bias[col], b1 = bias[col + 1];
            float v00 = c[mt][nt][0] + b0, v01 = c[mt][nt][1] + b1;
            float v10 = c[mt][nt][2] + b0, v11 = c[mt][nt][3] + b1;
            if (sizeof(OutT) == 4) {
                *(float2*)&((float*)C)[(size_t)row * N + col] = make_float2(v00, v01);
                *(float2*)&((float*)C)[(size_t)(row + 8) * N + col] = make_float2(v10, v11);
            } else {
                *(__half2*)&((__half*)C)[(size_t)row * N + col] = __floats2half2_rn(v00, v01);
                *(__half2*)&((__half*)C)[(size_t)(row + 8) * N + col] = __floats2half2_rn(v10, v11);
            }
        }
    }
}

// ---------------------------------------------------------------------------
// Split QKV (fp16) + per-head LayerNorm on Q,K; copy V. fp16 head-major out.
// 8 lanes per row (each lane one uint4 = 8 halfs); 3-shuffle octet reduction.
// ---------------------------------------------------------------------------
__global__ __launch_bounds__(256) void qkv_split_ln8(
    const __half* __restrict__ qkv,
    const float* __restrict__ qg, const float* __restrict__ qb,
    const float* __restrict__ kg, const float* __restrict__ kb,
    __half* __restrict__ qh, __half* __restrict__ kh, __half* __restrict__ vh)
{
    const int oct = (blockIdx.x * blockDim.x + threadIdx.x) >> 3;  // row id
    const int l8  = threadIdx.x & 7;
    int t = oct / LN_ROWS_;      // 0:q 1:k 2:v
    int row = oct - t * LN_ROWS_;
    if (t >= 3) return;

    int b = row / (S_ * NH_);
    int rem = row - b * (S_ * NH_);
    int s = rem / NH_;
    int n = rem - s * NH_;

    const __half* src = qkv + (size_t)(b * S_ + s) * (3 * H_) + t * H_ + n * HD_ + l8 * 8;
    __half* dst = (t == 0 ? qh : (t == 1 ? kh : vh)) +
                  ((size_t)(b * NH_ + n) * S_ + s) * HD_ + l8 * 8;

    uint4 v = *(const uint4*)src;
    if (t == 2) { *(uint4*)dst = v; return; }

    __half2 hv[4];
    *(uint4*)hv = v;
    float x[8];
#pragma unroll
    for (int i = 0; i < 4; i++) {
        float2 f = __half22float2(hv[i]);
        x[2 * i] = f.x; x[2 * i + 1] = f.y;
    }

    float s1 = 0.f, s2 = 0.f;
#pragma unroll
    for (int i = 0; i < 8; i++) { s1 += x[i]; s2 += x[i] * x[i]; }
#pragma unroll
    for (int o = 1; o < 8; o <<= 1) {
        s1 += __shfl_xor_sync(0xffffffffu, s1, o);
        s2 += __shfl_xor_sync(0xffffffffu, s2, o);
    }
    float mu  = s1 * (1.0f / HD_);
    float var = s2 * (1.0f / HD_) - mu * mu;
    float inv = rsqrtf(var + 1e-5f);

    const float* g  = (t == 0) ? qg : kg;
    const float* be = (t == 0) ? qb : kb;
    float4 g0 = *(const float4*)&g[l8 * 8];
    float4 g1 = *(const float4*)&g[l8 * 8 + 4];
    float4 b0 = *(const float4*)&be[l8 * 8];
    float4 b1 = *(const float4*)&be[l8 * 8 + 4];

    __half2 o0 = __floats2half2_rn((x[0] - mu) * inv * g0.x + b0.x,
                                   (x[1] - mu) * inv * g0.y + b0.y);
    __half2 o1 = __floats2half2_rn((x[2] - mu) * inv * g0.z + b0.z,
                                   (x[3] - mu) * inv * g0.w + b0.w);
    __half2 o2 = __floats2half2_rn((x[4] - mu) * inv * g1.x + b1.x,
                                   (x[5] - mu) * inv * g1.y + b1.y);
    __half2 o3 = __floats2half2_rn((x[6] - mu) * inv * g1.z + b1.z,
                                   (x[7] - mu) * inv * g1.w + b1.w);
    uint4 ov;
    __half2 oh[4] = {o0, o1, o2, o3};
    ov = *(uint4*)oh;
    *(uint4*)dst = ov;
}

// ---------------------------------------------------------------------------
// Causal flash attention, fp16 tensor cores. ctx written as fp16.
// K and V fragment loads via x4 ldmatrix (8 LDSM per tile each).
// ---------------------------------------------------------------------------
#define QST 72
#define KST 72
#define VST 72

__global__ __launch_bounds__(256, 2) void flash_attn_fp16(
    const __half* __restrict__ qh, const __half* __restrict__ kh,
    const __half* __restrict__ vh, __half* __restrict__ ctx)
{
    __shared__ __half Qs[128][QST];
    __shared__ __half Ks[32][KST];
    __shared__ __half Vs[32][VST];

    const int bh  = blockIdx.y;
    const int qt  = blockIdx.x;
    const int tid = threadIdx.x;
    const int lane = tid & 31;
    const int w    = tid >> 5;
    const int gid  = lane >> 2;
    const int tig  = lane & 3;
    const int l8   = lane & 7;
    const int h8   = (lane >> 3) & 1;
    const int h16  = (lane >> 4) & 1;
    const int qbase = qt * 128;
    const int wrow  = w * 16;

    const __half* Q  = qh + (size_t)bh * S_ * HD_ + (size_t)qbase * HD_;
    const __half* Kp = kh + (size_t)bh * S_ * HD_;
    const __half* Vp = vh + (size_t)bh * S_ * HD_;

    for (int i = tid; i < 128 * 8; i += 256) {
        int r = i >> 3, c8 = (i & 7) * 8;
        *(uint4*)&Qs[r][c8] = *(const uint4*)&Q[r * HD_ + c8];
    }
    __syncthreads();

    const uint32_t qsB = (uint32_t)__cvta_generic_to_shared(&Qs[0][0]) +
                         ((uint32_t)(wrow + l8 + h8 * 8) * QST + h16 * 8) * 2;
    uint32_t qa[4][4];
#pragma unroll
    for (int ks = 0; ks < 4; ks++)
        ldsm_x4(qa[ks], qsB + (uint32_t)(ks * 16) * 2);
    __syncthreads();

    // K x4 (non-trans): lanes 0-15 -> key rows l8 (+k-col h8*8);
    //                   lanes 16-31 -> key rows l8+8 (next 8-key block)
    const uint32_t ksB = (uint32_t)__cvta_generic_to_shared(&Ks[0][0]) +
                         ((uint32_t)(l8 + h16 * 8) * KST + h8 * 8) * 2;
    // V x4 (trans): lanes 0-15 -> k rows l8+h8*8 at col 0;
    //               lanes 16-31 -> same rows at col +8 (next n block)
    const uint32_t vsB = (uint32_t)__cvta_generic_to_shared(&Vs[0][0]) +
                         ((uint32_t)(l8 + h8 * 8) * VST + h16 * 8) * 2;

    float o[8][4];
#pragma unroll
    for (int i = 0; i < 8; i++)
#pragma unroll
        for (int j = 0; j < 4; j++) o[i][j] = 0.f;
    float m0 = -CUDART_INF_F, m1 = -CUDART_INF_F;
    float l0 = 0.f, l1 = 0.f;

    const int r0g = qbase + wrow + gid;
    const int r1g = r0g + 8;
    const int rmaxw = qbase + wrow + 15;
    const int nkt = (qt + 1) * 4;
    const float scl = 0.125f;

    for (int kt = 0; kt < nkt; kt++) {
        const int kbase = kt * 32;
        {
            int r = tid >> 3, c8 = (tid & 7) * 8;
            *(uint4*)&Ks[r][c8] = *(const uint4*)&Kp[(size_t)(kbase + r) * HD_ + c8];
            *(uint4*)&Vs[r][c8] = *(const uint4*)&Vp[(size_t)(kbase + r) * HD_ + c8];
        }
        __syncthreads();

        if (kbase <= rmaxw) {
            float s[4][4];
#pragma unroll
            for (int nt = 0; nt < 4; nt++)
#pragma unroll
                for (int j = 0; j < 4; j++) s[nt][j] = 0.f;
#pragma unroll
            for (int np = 0; np < 2; np++) {
#pragma unroll
                for (int ks = 0; ks < 4; ks++) {
                    uint32_t b4[4];
                    ldsm_x4(b4, ksB + (uint32_t)(np * 16 * KST + ks * 16) * 2);
                    mma_fp16(s[2 * np],     qa[ks], &b4[0]);
                    mma_fp16(s[2 * np + 1], qa[ks], &b4[2]);
                }
            }

            if (kbase + 31 <= qbase + wrow) {
#pragma unroll
                for (int nt = 0; nt < 4; nt++)
#pragma unroll
                    for (int j = 0; j < 4; j++) s[nt][j] *= scl;
            } else {
#pragma unroll
                for (int nt = 0; nt < 4; nt++) {
                    int c0 = kbase + nt * 8 + tig * 2;
                    s[nt][0] = (c0     <= r0g) ? s[nt][0] * scl : -CUDART_INF_F;
                    s[nt][1] = (c0 + 1 <= r0g) ? s[nt][1] * scl : -CUDART_INF_F;
                    s[nt][2] = (c0     <= r1g) ? s[nt][2] * scl : -CUDART_INF_F;
                    s[nt][3] = (c0 + 1 <= r1g) ? s[nt][3] * scl : -CUDART_INF_F;
                }
            }

            float mt0 = fmaxf(fmaxf(s[0][0], s[0][1]), fmaxf(s[1][0], s[1][1]));
            mt0 = fmaxf(mt0, fmaxf(fmaxf(s[2][0], s[2][1]), fmaxf(s[3][0], s[3][1])));
            float mt1 = fmaxf(fmaxf(s[0][2], s[0][3]), fmaxf(s[1][2], s[1][3]));
            mt1 = fmaxf(mt1, fmaxf(fmaxf(s[2][2], s[2][3]), fmaxf(s[3][2], s[3][3])));
            mt0 = fmaxf(mt0, __shfl_xor_sync(0xffffffffu, mt0, 1));
            mt0 = fmaxf(mt0, __shfl_xor_sync(0xffffffffu, mt0, 2));
            mt1 = fmaxf(mt1, __shfl_xor_sync(0xffffffffu, mt1, 1));
            mt1 = fmaxf(mt1, __shfl_xor_sync(0xffffffffu, mt1, 2));

            float mn0 = fmaxf(m0, mt0), mn1 = fmaxf(m1, mt1);
            float a0 = __expf(m0 - mn0), a1 = __expf(m1 - mn1);
            m0 = mn0; m1 = mn1;

            float p[4][4];
            float ps0 = 0.f, ps1 = 0.f;
#pragma unroll
            for (int nt = 0; nt < 4; nt++) {
                p[nt][0] = __expf(s[nt][0] - mn0);
                p[nt][1] = __expf(s[nt][1] - mn0);
                p[nt][2] = __expf(s[nt][2] - mn1);
                p[nt][3] = __expf(s[nt][3] - mn1);
                ps0 += p[nt][0] + p[nt][1];
                ps1 += p[nt][2] + p[nt][3];
            }
            ps0 += __shfl_xor_sync(0xffffffffu, ps0, 1);
            ps0 += __shfl_xor_sync(0xffffffffu, ps0, 2);
            ps1 += __shfl_xor_sync(0xffffffffu, ps1, 1);
            ps1 += __shfl_xor_sync(0xffffffffu, ps1, 2);
            l0 = l0 * a0 + ps0;
            l1 = l1 * a1 + ps1;

            uint32_t pa[2][4];
#pragma unroll
            for (int ks = 0; ks < 2; ks++) {
                pa[ks][0] = h2r(p[2 * ks][0],     p[2 * ks][1]);
                pa[ks][1] = h2r(p[2 * ks][2],     p[2 * ks][3]);
                pa[ks][2] = h2r(p[2 * ks + 1][0], p[2 * ks + 1][1]);
                pa[ks][3] = h2r(p[2 * ks + 1][2], p[2 * ks + 1][3]);
            }

#pragma unroll
            for (int nt = 0; nt < 8; nt++) {
                o[nt][0] *= a0; o[nt][1] *= a0;
                o[nt][2] *= a1; o[nt][3] *= a1;
            }
#pragma unroll
            for (int np = 0; np < 4; np++) {
#pragma unroll
                for (int ks = 0; ks < 2; ks++) {
                    uint32_t b4[4];
                    ldsm_x4_t(b4, vsB + (uint32_t)(ks * 16 * VST + np * 16) * 2);
                    mma_fp16(o[2 * np],     pa[ks], &b4[0]);
                    mma_fp16(o[2 * np + 1], pa[ks], &b4[2]);
                }
            }
        }
        __syncthreads();
    }

    const int bb = bh >> 4;
    const int nh = bh & 15;
    const float inv0 = 1.0f / l0;
    const float inv1 = 1.0f / l1;
    __half* orow0 = ctx + (size_t)(bb * S_ + r0g) * H_ + nh * HD_;
    __half* orow1 = ctx + (size_t)(bb * S_ + r1g) * H_ + nh * HD_;
#pragma unroll
    for (int nt = 0; nt < 8; nt++) {
        int col = nt * 8 + tig * 2;
        *(__half2*)&orow0[col] = __floats2half2_rn(o[nt][0] * inv0, o[nt][1] * inv0);
        *(__half2*)&orow1[col] = __floats2half2_rn(o[nt][2] * inv1, o[nt][3] * inv1);
    }
}

// ---------------------------------------------------------------------------
extern "C" void kernel_launch(void* const* d_in, const int* in_sizes, int n_in,
                              void* d_out, int out_size)
{
    const float* hs = (const float*)d_in[0];
    const float* Wa = (const float*)d_in[1];
    const float* ba = (const float*)d_in[2];
    const float* Wp = (const float*)d_in[3];
    const float* bp = (const float*)d_in[4];
    const float* qg = (const float*)d_in[5];
    const float* qb = (const float*)d_in[6];
    const float* kg = (const float*)d_in[7];
    const float* kb = (const float*)d_in[8];
    float* out = (float*)d_out;

    __half *qkvh, *hsh, *wah, *wph, *qh, *kh, *vh, *ctxh;
    cudaGetSymbolAddress((void**)&qkvh, g_qkvh);
    cudaGetSymbolAddress((void**)&hsh, g_hsh);
    cudaGetSymbolAddress((void**)&wah, g_wah);
    cudaGetSymbolAddress((void**)&wph, g_wph);
    cudaGetSymbolAddress((void**)&qh,  g_qh);
    cudaGetSymbolAddress((void**)&kh,  g_kh);
    cudaGetSymbolAddress((void**)&vh,  g_vh);
    cudaGetSymbolAddress((void**)&ctxh, g_ctxh);

    // 0) fp32 -> fp16 input conversions
    {
        int n4;
        n4 = (MROWS_ * H_) / 4;
        f2h<<<(n4 + 255) / 256, 256>>>((const float4*)hs, (uint2*)hsh, n4);
        n4 = (H_ * 3 * H_) / 4;
        f2h<<<(n4 + 255) / 256, 256>>>((const float4*)Wa, (uint2*)wah, n4);
        n4 = (H_ * H_) / 4;
        f2h<<<(n4 + 255) / 256, 256>>>((const float4*)Wp, (uint2*)wph, n4);
    }

    // 1) QKV GEMM (fp16 out): [4096,1024] @ [1024,3072] + bias
    gemm_fp16p<__half><<<dim3(3 * H_ / 128, MROWS_ / 128), 256>>>(
        hsh, wah, ba, qkvh, MROWS_, 3 * H_, H_);

    // 2) split + QK layernorm + V copy (8 lanes/row)
    {
        int threads_total = 3 * LN_ROWS_ * 8;
        qkv_split_ln8<<<threads_total / 256, 256>>>(qkvh, qg, qb, kg, kb, qh, kh, vh);
    }

    // 3) causal flash attention (fp16; ctx fp16)
    flash_attn_fp16<<<dim3(S_ / 128, B_ * NH_), 256>>>(qh, kh, vh, ctxh);

    // 4) output projection (fp32 out): [4096,1024] @ [1024,1024] + bias
    gemm_fp16p<float><<<dim3(H_ / 128, MROWS_ / 128), 256>>>(
        ctxh, wph, bp, out, MROWS_, H_, H_);
}